// round 11
// baseline (speedup 1.0000x reference)
#include <cuda_runtime.h>
#include <math.h>

// ---------------------------------------------------------------------------
// SlotAttention on GB300 — tf32 tensor-core GEMMs + SIMT attention (S=8).
// B=32, F=4096, S=8, D=512, H=2048, 3 iterations.
// d_out layout: [0 : 256*512) slots, [256*512 : +32*8*4096) pre_norm_attn.
// ---------------------------------------------------------------------------

namespace {
constexpr int kB = 32, kF = 4096, kS = 8, kD = 512, kH = 2048;
constexpr int kBS = kB * kS;       // 256
constexpr int kBF = kB * kF;       // 131072
constexpr float kEPS   = 1e-8f;
constexpr float kLNEPS = 1e-5f;
constexpr float kSCALE = 0.04419417382415922f;  // D^-0.5
}

// ------------------------------ scratch (no cudaMalloc allowed) -------------
__device__ float g_fln[(size_t)kBF * kD];     // LN(features)        268 MB
__device__ float g_keys[(size_t)kBF * kD];    // keys                268 MB
__device__ float g_values[(size_t)kBF * kD];  // values              268 MB
__device__ float g_sn[kBS * kD];
__device__ float g_q[kBS * kD];
__device__ float g_updates[kBS * kD];
__device__ float g_upart[8 * kBS * kD];       // partial updates     4 MB
__device__ float g_gi[kBS * 3 * kD];
__device__ float g_gh[kBS * 3 * kD];
__device__ float g_slots[kBS * kD];
__device__ float g_tbuf[kBS * kD];
__device__ float g_h1[kBS * kH];
__device__ float g_rowsum[kBS];

// ------------------------------ LayerNorm (row length 512) ------------------
__global__ __launch_bounds__(128) void ln_kernel(
    const float* __restrict__ x, const float* __restrict__ w,
    const float* __restrict__ b, float* __restrict__ y)
{
    const int row = blockIdx.x;
    const int tid = threadIdx.x;
    const float4 v = ((const float4*)(x + (size_t)row * kD))[tid];
    float s  = v.x + v.y + v.z + v.w;
    float sq = v.x * v.x + v.y * v.y + v.z * v.z + v.w * v.w;
    const int lane = tid & 31, wid = tid >> 5;
#pragma unroll
    for (int o = 16; o; o >>= 1) {
        s  += __shfl_xor_sync(0xffffffffu, s, o);
        sq += __shfl_xor_sync(0xffffffffu, sq, o);
    }
    __shared__ float rs[4], rq[4];
    if (lane == 0) { rs[wid] = s; rq[wid] = sq; }
    __syncthreads();
    const float st = rs[0] + rs[1] + rs[2] + rs[3];
    const float qt = rq[0] + rq[1] + rq[2] + rq[3];
    const float m = st * (1.0f / kD);
    const float var = qt * (1.0f / kD) - m * m;
    const float rstd = rsqrtf(var + kLNEPS);
    const float4 wv = ((const float4*)w)[tid];
    const float4 bv = ((const float4*)b)[tid];
    float4 o4;
    o4.x = (v.x - m) * rstd * wv.x + bv.x;
    o4.y = (v.y - m) * rstd * wv.y + bv.y;
    o4.z = (v.z - m) * rstd * wv.z + bv.z;
    o4.w = (v.w - m) * rstd * wv.w + bv.w;
    ((float4*)(y + (size_t)row * kD))[tid] = o4;
}

// ------------------------------ generic tf32 GEMM ---------------------------
// C[M,N] = act(A[M,K] @ B + bias) (+ resid)
// bT=0: B stored [K,N];  bT=1: B stored [N,K] (C = A @ B^T)
// Requires M%128==0, N%128==0, K%32==0 (true for all call sites).

__device__ __forceinline__ unsigned f2tf(float x) {
    unsigned r;
    asm("cvt.rna.tf32.f32 %0, %1;" : "=r"(r) : "f"(x));
    return r;
}

__device__ __forceinline__ void mma8(float c[4], const unsigned a[4], const unsigned b[2]) {
    asm volatile(
        "mma.sync.aligned.m16n8k8.row.col.f32.tf32.tf32.f32 "
        "{%0,%1,%2,%3}, {%4,%5,%6,%7}, {%8,%9}, {%0,%1,%2,%3};\n"
        : "+f"(c[0]), "+f"(c[1]), "+f"(c[2]), "+f"(c[3])
        : "r"(a[0]), "r"(a[1]), "r"(a[2]), "r"(a[3]), "r"(b[0]), "r"(b[1]));
}

#define GBM 128
#define GBN 128
#define GBK 32

__global__ __launch_bounds__(256) void gemm_kernel(
    const float* __restrict__ A, const float* __restrict__ Bmat,
    float* __restrict__ C, int M, int N, int K, int bT,
    const float* __restrict__ bias, int relu, const float* __restrict__ resid)
{
    __shared__ unsigned As[GBM][36];
    __shared__ unsigned Bs[GBK][136];
    const int bm0 = blockIdx.x * GBM;
    const int bn0 = blockIdx.y * GBN;
    const int tid = threadIdx.x;
    const int lane = tid & 31;
    const int wid = tid >> 5;
    const int wm = wid >> 2, wn = wid & 3;        // 2 x 4 warp grid
    const int g = lane >> 2, tig = lane & 3;

    float acc[4][4][4];
#pragma unroll
    for (int i = 0; i < 4; ++i)
#pragma unroll
        for (int j = 0; j < 4; ++j)
#pragma unroll
            for (int l = 0; l < 4; ++l) acc[i][j][l] = 0.0f;

    for (int k0 = 0; k0 < K; k0 += GBK) {
#pragma unroll
        for (int i = 0; i < 4; ++i) {               // A tile 128x32
            const int qq = tid + i * 256;
            const int row = qq >> 3;
            const int kc = (qq & 7) << 2;
            const float4 v = *(const float4*)(A + (size_t)(bm0 + row) * K + k0 + kc);
            uint4 t; t.x = f2tf(v.x); t.y = f2tf(v.y); t.z = f2tf(v.z); t.w = f2tf(v.w);
            *(uint4*)&As[row][kc] = t;
        }
        if (!bT) {
#pragma unroll
            for (int i = 0; i < 4; ++i) {           // B tile 32x128
                const int qq = tid + i * 256;
                const int r = qq >> 5;
                const int c = (qq & 31) << 2;
                const float4 v = *(const float4*)(Bmat + (size_t)(k0 + r) * N + bn0 + c);
                uint4 t; t.x = f2tf(v.x); t.y = f2tf(v.y); t.z = f2tf(v.z); t.w = f2tf(v.w);
                *(uint4*)&Bs[r][c] = t;
            }
        } else {
#pragma unroll
            for (int i = 0; i < 4; ++i) {           // B^T: rows are N
                const int qq = tid + i * 256;
                const int n = qq >> 3;
                const int kc = (qq & 7) << 2;
                const float4 v = *(const float4*)(Bmat + (size_t)(bn0 + n) * K + k0 + kc);
                Bs[kc + 0][n] = f2tf(v.x);
                Bs[kc + 1][n] = f2tf(v.y);
                Bs[kc + 2][n] = f2tf(v.z);
                Bs[kc + 3][n] = f2tf(v.w);
            }
        }
        __syncthreads();
#pragma unroll
        for (int kk = 0; kk < GBK; kk += 8) {
            unsigned af[4][4], bf[4][2];
#pragma unroll
            for (int mf = 0; mf < 4; ++mf) {
                const int r = wm * 64 + mf * 16;
                af[mf][0] = As[r + g][kk + tig];
                af[mf][1] = As[r + g + 8][kk + tig];
                af[mf][2] = As[r + g][kk + tig + 4];
                af[mf][3] = As[r + g + 8][kk + tig + 4];
            }
#pragma unroll
            for (int nf = 0; nf < 4; ++nf) {
                const int c = wn * 32 + nf * 8 + g;
                bf[nf][0] = Bs[kk + tig][c];
                bf[nf][1] = Bs[kk + tig + 4][c];
            }
#pragma unroll
            for (int mf = 0; mf < 4; ++mf)
#pragma unroll
                for (int nf = 0; nf < 4; ++nf)
                    mma8(acc[mf][nf], af[mf], bf[nf]);
        }
        __syncthreads();
    }

#pragma unroll
    for (int mf = 0; mf < 4; ++mf) {
#pragma unroll
        for (int nf = 0; nf < 4; ++nf) {
            const int row0 = bm0 + wm * 64 + mf * 16 + g;
            const int col  = bn0 + wn * 32 + nf * 8 + tig * 2;
            float bb0 = 0.f, bb1 = 0.f;
            if (bias) { bb0 = bias[col]; bb1 = bias[col + 1]; }
#pragma unroll
            for (int h = 0; h < 2; ++h) {
                const int r = row0 + h * 8;
                float x0 = acc[mf][nf][h * 2 + 0] + bb0;
                float x1 = acc[mf][nf][h * 2 + 1] + bb1;
                if (relu) { x0 = fmaxf(x0, 0.f); x1 = fmaxf(x1, 0.f); }
                const size_t o = (size_t)r * N + col;
                if (resid) { x0 += resid[o]; x1 += resid[o + 1]; }
                C[o]     = x0;
                C[o + 1] = x1;
            }
        }
    }
}

// -------------------- dots + softmax-over-slots + rowsum --------------------
// grid (F/8, B), block 256: one warp per f. q[b] cached in smem.
__global__ __launch_bounds__(256) void dots_kernel(
    const float* __restrict__ q, const float* __restrict__ keys,
    float* __restrict__ attn, float* __restrict__ rowsum)
{
    const int b = blockIdx.y;
    __shared__ float4 qsm[kS * kD / 4];   // 1024 float4 = 16 KB
    const int tid = threadIdx.x;
    const float4* qg = (const float4*)(q + (size_t)b * kS * kD);
#pragma unroll
    for (int i = 0; i < 4; ++i) qsm[tid + i * 256] = qg[tid + i * 256];
    __syncthreads();

    const int w = tid >> 5, lane = tid & 31;
    const int f = blockIdx.x * 8 + w;
    const float4* kr = (const float4*)(keys + ((size_t)b * kF + f) * kD);
    float acc[8];
#pragma unroll
    for (int s = 0; s < 8; ++s) acc[s] = 0.f;
#pragma unroll
    for (int c = 0; c < 4; ++c) {
        const float4 kv = kr[lane + c * 32];
#pragma unroll
        for (int s = 0; s < 8; ++s) {
            const float4 qv = qsm[s * 128 + lane + c * 32];
            acc[s] += kv.x * qv.x + kv.y * qv.y + kv.z * qv.z + kv.w * qv.w;
        }
    }
#pragma unroll
    for (int s = 0; s < 8; ++s)
#pragma unroll
        for (int o = 16; o; o >>= 1)
            acc[s] += __shfl_xor_sync(0xffffffffu, acc[s], o);

    // softmax over the 8 slots (redundant across lanes)
    float mx = -1e30f;
#pragma unroll
    for (int s = 0; s < 8; ++s) mx = fmaxf(mx, acc[s] * kSCALE);
    float e[8], tot = 0.f;
#pragma unroll
    for (int s = 0; s < 8; ++s) { e[s] = __expf(acc[s] * kSCALE - mx); tot += e[s]; }
    const float inv = 1.f / tot;

    __shared__ float psum[8][9];
    if (lane < 8) {
        const float p = e[lane] * inv;
        attn[(size_t)b * kS * kF + (size_t)lane * kF + f] = p;
        psum[lane][w] = p;
    }
    __syncthreads();
    if (tid < 8) {
        float t = 0.f;
#pragma unroll
        for (int w2 = 0; w2 < 8; ++w2) t += psum[tid][w2];
        atomicAdd(&rowsum[b * kS + tid], t);
    }
}

// -------------------- updates = attn_norm @ values (partials) ---------------
// grid (8 chunks of 512 f, B), block 256: thread owns 2 d-cols for all 8 s.
__global__ __launch_bounds__(256) void upd_kernel(
    const float* __restrict__ attn, const float* __restrict__ values,
    const float* __restrict__ rowsum, float* __restrict__ upart)
{
    const int b = blockIdx.y, chunk = blockIdx.x;
    const int tid = threadIdx.x;
    __shared__ float wsm[8][64];
    __shared__ float inv[8];
    if (tid < 8) inv[tid] = 1.f / (rowsum[b * kS + tid] + (float)kF * kEPS);

    float acc[8][2];
#pragma unroll
    for (int s = 0; s < 8; ++s) { acc[s][0] = 0.f; acc[s][1] = 0.f; }
    float vs0 = 0.f, vs1 = 0.f;
    const int f0 = chunk * 512;
    const int d0 = tid * 2;
    const size_t abase = (size_t)b * kS * kF;

    for (int ft = 0; ft < 512; ft += 64) {
        __syncthreads();
        {
            int idx = tid;
            wsm[idx >> 6][idx & 63] = attn[abase + (size_t)(idx >> 6) * kF + f0 + ft + (idx & 63)];
            idx = tid + 256;
            wsm[idx >> 6][idx & 63] = attn[abase + (size_t)(idx >> 6) * kF + f0 + ft + (idx & 63)];
        }
        __syncthreads();
        for (int j = 0; j < 64; ++j) {
            const int f = f0 + ft + j;
            const float2 v = *(const float2*)(values + ((size_t)b * kF + f) * kD + d0);
            vs0 += v.x; vs1 += v.y;
#pragma unroll
            for (int s = 0; s < 8; ++s) {
                const float wv = wsm[s][j];
                acc[s][0] += wv * v.x;
                acc[s][1] += wv * v.y;
            }
        }
    }
#pragma unroll
    for (int s = 0; s < 8; ++s) {
        const float iv = inv[s];
        const size_t o = ((size_t)(chunk * kBS + b * kS + s)) * kD + d0;
        upart[o]     = (acc[s][0] + kEPS * vs0) * iv;
        upart[o + 1] = (acc[s][1] + kEPS * vs1) * iv;
    }
}

__global__ __launch_bounds__(128) void upd_reduce(
    const float* __restrict__ upart, float* __restrict__ updates)
{
    const int bs = blockIdx.x, tid = threadIdx.x;
    float4 a = make_float4(0.f, 0.f, 0.f, 0.f);
#pragma unroll
    for (int c = 0; c < 8; ++c) {
        const float4 v = *(const float4*)(upart + ((size_t)(c * kBS + bs)) * kD + tid * 4);
        a.x += v.x; a.y += v.y; a.z += v.z; a.w += v.w;
    }
    *(float4*)(updates + (size_t)bs * kD + tid * 4) = a;
}

// -------------------- GRU gate combine ---------------------------------------
__global__ __launch_bounds__(256) void gru_kernel(
    const float* __restrict__ gi, const float* __restrict__ gh,
    const float* __restrict__ hprev, float* __restrict__ out)
{
    const int i = blockIdx.x * 256 + threadIdx.x;       // 131072 total
    const int bs = i >> 9, d = i & 511;
    const size_t base = (size_t)bs * (3 * kD) + d;
    const float ir = gi[base], iz = gi[base + kD], in_ = gi[base + 2 * kD];
    const float hr = gh[base], hz = gh[base + kD], hn  = gh[base + 2 * kD];
    const float r = 1.f / (1.f + __expf(-(ir + hr)));
    const float z = 1.f / (1.f + __expf(-(iz + hz)));
    const float n = tanhf(in_ + r * hn);
    out[i] = (1.f - z) * n + z * hprev[i];
}

// -------------------- utility kernels ----------------------------------------
__global__ void zero_kernel(float* p, int n) {
    const int i = blockIdx.x * blockDim.x + threadIdx.x;
    if (i < n) p[i] = 0.f;
}
__global__ void copy4_kernel(float4* __restrict__ dst, const float4* __restrict__ src, int n4) {
    const int i = blockIdx.x * blockDim.x + threadIdx.x;
    if (i < n4) dst[i] = src[i];
}

// -------------------- host launcher ------------------------------------------
static void gemm(const float* A, const float* B, float* C, int M, int N, int K,
                 int bT, const float* bias, int relu, const float* resid)
{
    dim3 grid(M / GBM, N / GBN);
    gemm_kernel<<<grid, 256>>>(A, B, C, M, N, K, bT, bias, relu, resid);
}

extern "C" void kernel_launch(void* const* d_in, const int* in_sizes, int n_in,
                              void* d_out, int out_size)
{
    const float* slots_in  = (const float*)d_in[0];
    const float* features  = (const float*)d_in[1];
    const float* w_k       = (const float*)d_in[2];
    const float* w_v       = (const float*)d_in[3];
    const float* w_q       = (const float*)d_in[4];
    const float* ln_feat_w = (const float*)d_in[5];
    const float* ln_feat_b = (const float*)d_in[6];
    const float* ln_slot_w = (const float*)d_in[7];
    const float* ln_slot_b = (const float*)d_in[8];
    const float* gru_w_ih  = (const float*)d_in[9];
    const float* gru_w_hh  = (const float*)d_in[10];
    const float* gru_b_ih  = (const float*)d_in[11];
    const float* gru_b_hh  = (const float*)d_in[12];
    const float* ln_mlp_w  = (const float*)d_in[13];
    const float* ln_mlp_b  = (const float*)d_in[14];
    const float* mlp_w1    = (const float*)d_in[15];
    const float* mlp_b1    = (const float*)d_in[16];
    const float* mlp_w2    = (const float*)d_in[17];
    const float* mlp_b2    = (const float*)d_in[18];

    float* out  = (float*)d_out;
    float* attn = out + kBS * kD;   // pre_norm_attn region [B,S,F]

    float *fln, *keys, *values, *sn, *q, *updates, *upart, *gi, *gh,
          *slots, *tbuf, *h1, *rowsum;
    cudaGetSymbolAddress((void**)&fln,     g_fln);
    cudaGetSymbolAddress((void**)&keys,    g_keys);
    cudaGetSymbolAddress((void**)&values,  g_values);
    cudaGetSymbolAddress((void**)&sn,      g_sn);
    cudaGetSymbolAddress((void**)&q,       g_q);
    cudaGetSymbolAddress((void**)&updates, g_updates);
    cudaGetSymbolAddress((void**)&upart,   g_upart);
    cudaGetSymbolAddress((void**)&gi,      g_gi);
    cudaGetSymbolAddress((void**)&gh,      g_gh);
    cudaGetSymbolAddress((void**)&slots,   g_slots);
    cudaGetSymbolAddress((void**)&tbuf,    g_tbuf);
    cudaGetSymbolAddress((void**)&h1,      g_h1);
    cudaGetSymbolAddress((void**)&rowsum,  g_rowsum);

    // prologue: slots copy, LN(features), keys, values
    copy4_kernel<<<(kBS * kD / 4 + 255) / 256, 256>>>((float4*)slots, (const float4*)slots_in, kBS * kD / 4);
    ln_kernel<<<kBF, 128>>>(features, ln_feat_w, ln_feat_b, fln);
    gemm(fln, w_k, keys,   kBF, kD, kD, 0, nullptr, 0, nullptr);
    gemm(fln, w_v, values, kBF, kD, kD, 0, nullptr, 0, nullptr);

    for (int it = 0; it < 3; ++it) {
        ln_kernel<<<kBS, 128>>>(slots, ln_slot_w, ln_slot_b, sn);
        gemm(sn, w_q, q, kBS, kD, kD, 0, nullptr, 0, nullptr);
        zero_kernel<<<1, 256>>>(rowsum, kBS);
        dots_kernel<<<dim3(kF / 8, kB), 256>>>(q, keys, attn, rowsum);
        upd_kernel<<<dim3(8, kB), 256>>>(attn, values, rowsum, upart);
        upd_reduce<<<kBS, 128>>>(upart, updates);
        gemm(updates, gru_w_ih, gi, kBS, 3 * kD, kD, 1, gru_b_ih, 0, nullptr);
        gemm(sn,      gru_w_hh, gh, kBS, 3 * kD, kD, 1, gru_b_hh, 0, nullptr);
        gru_kernel<<<kBS * kD / 256, 256>>>(gi, gh, sn, slots);
        ln_kernel<<<kBS, 128>>>(slots, ln_mlp_w, ln_mlp_b, tbuf);
        gemm(tbuf, mlp_w1, h1, kBS, kH, kD, 0, mlp_b1, 1, nullptr);
        gemm(h1, mlp_w2, slots, kBS, kD, kH, 0, mlp_b2, 0, slots);
    }

    copy4_kernel<<<(kBS * kD / 4 + 255) / 256, 256>>>((float4*)out, (const float4*)slots, kBS * kD / 4);
}

// round 12
// speedup vs baseline: 1.4477x; 1.4477x over previous
#include <cuda_runtime.h>
#include <math.h>

// ---------------------------------------------------------------------------
// SlotAttention on GB300 — round 2: fused+pipelined KV GEMM, split-K small GEMMs
// B=32, F=4096, S=8, D=512, H=2048, 3 iterations.
// d_out layout: [0 : 256*512) slots, [256*512 : +32*8*4096) pre_norm_attn.
// ---------------------------------------------------------------------------

namespace {
constexpr int kB = 32, kF = 4096, kS = 8, kD = 512, kH = 2048;
constexpr int kBS = kB * kS;       // 256
constexpr int kBF = kB * kF;       // 131072
constexpr int kKV = 1024;          // fused K|V row stride
constexpr float kEPS   = 1e-8f;
constexpr float kLNEPS = 1e-5f;
constexpr float kSCALE = 0.04419417382415922f;  // D^-0.5
}

// ------------------------------ scratch (no cudaMalloc allowed) -------------
__device__ float g_fln[(size_t)kBF * kD];     // LN(features)   268 MB
__device__ float g_kv[(size_t)kBF * kKV];     // keys|values    536 MB
__device__ float g_wkv[kD * kKV];             // packed weights 2 MB
__device__ float g_sn[kBS * kD];
__device__ float g_q[kBS * kD];
__device__ float g_updates[kBS * kD];
__device__ float g_upart[8 * kBS * kD];
__device__ float g_gi[kBS * 3 * kD];
__device__ float g_gh[kBS * 3 * kD];
__device__ float g_slots[kBS * kD];
__device__ float g_tbuf[kBS * kD];
__device__ float g_h1[kBS * kH];
__device__ float g_rowsum[kBS];
__device__ float g_part[2 * 1024 * 1024];     // split-K partials 8 MB

// ------------------------------ LayerNorm (row length 512) ------------------
__global__ __launch_bounds__(128) void ln_kernel(
    const float* __restrict__ x, const float* __restrict__ w,
    const float* __restrict__ b, float* __restrict__ y)
{
    const int row = blockIdx.x;
    const int tid = threadIdx.x;
    const float4 v = ((const float4*)(x + (size_t)row * kD))[tid];
    float s  = v.x + v.y + v.z + v.w;
    float sq = v.x * v.x + v.y * v.y + v.z * v.z + v.w * v.w;
    const int lane = tid & 31, wid = tid >> 5;
#pragma unroll
    for (int o = 16; o; o >>= 1) {
        s  += __shfl_xor_sync(0xffffffffu, s, o);
        sq += __shfl_xor_sync(0xffffffffu, sq, o);
    }
    __shared__ float rs[4], rq[4];
    if (lane == 0) { rs[wid] = s; rq[wid] = sq; }
    __syncthreads();
    const float st = rs[0] + rs[1] + rs[2] + rs[3];
    const float qt = rq[0] + rq[1] + rq[2] + rq[3];
    const float m = st * (1.0f / kD);
    const float var = qt * (1.0f / kD) - m * m;
    const float rstd = rsqrtf(var + kLNEPS);
    const float4 wv = ((const float4*)w)[tid];
    const float4 bv = ((const float4*)b)[tid];
    float4 o4;
    o4.x = (v.x - m) * rstd * wv.x + bv.x;
    o4.y = (v.y - m) * rstd * wv.y + bv.y;
    o4.z = (v.z - m) * rstd * wv.z + bv.z;
    o4.w = (v.w - m) * rstd * wv.w + bv.w;
    ((float4*)(y + (size_t)row * kD))[tid] = o4;
}

// ------------------------------ tf32 helpers --------------------------------
__device__ __forceinline__ unsigned f2tf(float x) {
    unsigned r;
    asm("cvt.rna.tf32.f32 %0, %1;" : "=r"(r) : "f"(x));
    return r;
}
__device__ __forceinline__ uint4 f2tf4(float4 v) {
    uint4 t; t.x = f2tf(v.x); t.y = f2tf(v.y); t.z = f2tf(v.z); t.w = f2tf(v.w);
    return t;
}
__device__ __forceinline__ void mma8(float c[4], const unsigned a[4], const unsigned b[2]) {
    asm volatile(
        "mma.sync.aligned.m16n8k8.row.col.f32.tf32.tf32.f32 "
        "{%0,%1,%2,%3}, {%4,%5,%6,%7}, {%8,%9}, {%0,%1,%2,%3};\n"
        : "+f"(c[0]), "+f"(c[1]), "+f"(c[2]), "+f"(c[3])
        : "r"(a[0]), "r"(a[1]), "r"(a[2]), "r"(a[3]), "r"(b[0]), "r"(b[1]));
}

// ------------------------------ big pipelined GEMM ---------------------------
// C[M,N] = A[M,K] @ B[K,N], tf32, 128x128x32 tiles, 2-stage register prefetch.
// Grid: (N/128, M/128) — n fastest so A tiles hit L2 across n-blocks.
#define GBM 128
#define GBN 128
#define GBK 32
#define ASZ (128 * 36)
#define BSZ (32 * 136)

__global__ __launch_bounds__(256) void gemm_big(
    const float* __restrict__ A, const float* __restrict__ Bmat,
    float* __restrict__ C, int M, int N, int K)
{
    extern __shared__ unsigned sm[];
    unsigned* AsBase = sm;              // 2 * ASZ
    unsigned* BsBase = sm + 2 * ASZ;    // 2 * BSZ
    const int bn0 = blockIdx.x * GBN;
    const int bm0 = blockIdx.y * GBM;
    const int tid = threadIdx.x;
    const int lane = tid & 31, wid = tid >> 5;
    const int wm = wid >> 2, wn = wid & 3;
    const int g = lane >> 2, tig = lane & 3;

    int arow[4], akc[4], brow[4], bcol[4];
#pragma unroll
    for (int i = 0; i < 4; ++i) {
        const int qq = tid + i * 256;
        arow[i] = qq >> 3;  akc[i]  = (qq & 7) << 2;
        brow[i] = qq >> 5;  bcol[i] = (qq & 31) << 2;
    }

    float4 ra[4], rb[4];
#pragma unroll
    for (int i = 0; i < 4; ++i) {
        ra[i] = *(const float4*)(A + (size_t)(bm0 + arow[i]) * K + akc[i]);
        rb[i] = *(const float4*)(Bmat + (size_t)brow[i] * N + bn0 + bcol[i]);
    }
#pragma unroll
    for (int i = 0; i < 4; ++i) {
        *(uint4*)&AsBase[arow[i] * 36 + akc[i]] = f2tf4(ra[i]);
        *(uint4*)&BsBase[brow[i] * 136 + bcol[i]] = f2tf4(rb[i]);
    }
    __syncthreads();

    float acc[4][4][4];
#pragma unroll
    for (int i = 0; i < 4; ++i)
#pragma unroll
        for (int j = 0; j < 4; ++j)
#pragma unroll
            for (int l = 0; l < 4; ++l) acc[i][j][l] = 0.0f;

    int cur = 0;
    for (int k0 = 0; k0 < K; k0 += GBK) {
        const int kn = k0 + GBK;
        if (kn < K) {
#pragma unroll
            for (int i = 0; i < 4; ++i) {
                ra[i] = *(const float4*)(A + (size_t)(bm0 + arow[i]) * K + kn + akc[i]);
                rb[i] = *(const float4*)(Bmat + (size_t)(kn + brow[i]) * N + bn0 + bcol[i]);
            }
        }
        const unsigned* As = AsBase + cur * ASZ;
        const unsigned* Bs = BsBase + cur * BSZ;
#pragma unroll
        for (int kk = 0; kk < GBK; kk += 8) {
            unsigned af[4][4], bf[4][2];
#pragma unroll
            for (int mf = 0; mf < 4; ++mf) {
                const int r = wm * 64 + mf * 16;
                af[mf][0] = As[(r + g) * 36 + kk + tig];
                af[mf][1] = As[(r + g + 8) * 36 + kk + tig];
                af[mf][2] = As[(r + g) * 36 + kk + tig + 4];
                af[mf][3] = As[(r + g + 8) * 36 + kk + tig + 4];
            }
#pragma unroll
            for (int nf = 0; nf < 4; ++nf) {
                const int c = wn * 32 + nf * 8 + g;
                bf[nf][0] = Bs[(kk + tig) * 136 + c];
                bf[nf][1] = Bs[(kk + tig + 4) * 136 + c];
            }
#pragma unroll
            for (int mf = 0; mf < 4; ++mf)
#pragma unroll
                for (int nf = 0; nf < 4; ++nf)
                    mma8(acc[mf][nf], af[mf], bf[nf]);
        }
        if (kn < K) {
            unsigned* An = AsBase + (cur ^ 1) * ASZ;
            unsigned* Bn = BsBase + (cur ^ 1) * BSZ;
#pragma unroll
            for (int i = 0; i < 4; ++i) {
                *(uint4*)&An[arow[i] * 36 + akc[i]] = f2tf4(ra[i]);
                *(uint4*)&Bn[brow[i] * 136 + bcol[i]] = f2tf4(rb[i]);
            }
        }
        __syncthreads();
        cur ^= 1;
    }

#pragma unroll
    for (int mf = 0; mf < 4; ++mf)
#pragma unroll
        for (int nf = 0; nf < 4; ++nf) {
            const int row0 = bm0 + wm * 64 + mf * 16 + g;
            const int col  = bn0 + wn * 32 + nf * 8 + tig * 2;
#pragma unroll
            for (int h = 0; h < 2; ++h) {
                float2 o2 = make_float2(acc[mf][nf][h * 2], acc[mf][nf][h * 2 + 1]);
                *(float2*)(C + (size_t)(row0 + h * 8) * N + col) = o2;
            }
        }
}

// ------------------------------ small split-K GEMM ---------------------------
// 64x64x32 tile, 128 threads (2x2 warps, warp tile 32x32).
// Grid (M/64, N/64, SK); each z computes Kc=K/SK and writes partials.
// BT=1: B stored [N,K] (C = A @ B^T).
template <int BT>
__global__ __launch_bounds__(128) void gemm_small(
    const float* __restrict__ A, const float* __restrict__ Bmat,
    float* __restrict__ Cpart, int M, int N, int K, int Kc)
{
    __shared__ unsigned As[64][36];
    __shared__ unsigned Bsm[2304];   // !BT: [32][72]; BT: [64][36]
    const int bm0 = blockIdx.x * 64;
    const int bn0 = blockIdx.y * 64;
    const int tid = threadIdx.x;
    const int lane = tid & 31, wid = tid >> 5;
    const int wm = wid >> 1, wn = wid & 1;
    const int g = lane >> 2, tig = lane & 3;

    float acc[2][4][4];
#pragma unroll
    for (int i = 0; i < 2; ++i)
#pragma unroll
        for (int j = 0; j < 4; ++j)
#pragma unroll
            for (int l = 0; l < 4; ++l) acc[i][j][l] = 0.0f;

    const int kbeg = blockIdx.z * Kc;
    for (int k0 = kbeg; k0 < kbeg + Kc; k0 += 32) {
#pragma unroll
        for (int i = 0; i < 4; ++i) {
            const int qq = tid + i * 128;
            const int row = qq >> 3, kc = (qq & 7) << 2;
            const float4 v = *(const float4*)(A + (size_t)(bm0 + row) * K + k0 + kc);
            *(uint4*)&As[row][kc] = f2tf4(v);
        }
        if (!BT) {
#pragma unroll
            for (int i = 0; i < 4; ++i) {
                const int qq = tid + i * 128;
                const int r = qq >> 4, c = (qq & 15) << 2;
                const float4 v = *(const float4*)(Bmat + (size_t)(k0 + r) * N + bn0 + c);
                *(uint4*)&Bsm[r * 72 + c] = f2tf4(v);
            }
        } else {
#pragma unroll
            for (int i = 0; i < 4; ++i) {
                const int qq = tid + i * 128;
                const int n = qq >> 3, kc = (qq & 7) << 2;
                const float4 v = *(const float4*)(Bmat + (size_t)(bn0 + n) * K + k0 + kc);
                *(uint4*)&Bsm[n * 36 + kc] = f2tf4(v);
            }
        }
        __syncthreads();
#pragma unroll
        for (int kk = 0; kk < 32; kk += 8) {
            unsigned af[2][4], bf[4][2];
#pragma unroll
            for (int mf = 0; mf < 2; ++mf) {
                const int r = wm * 32 + mf * 16;
                af[mf][0] = As[r + g][kk + tig];
                af[mf][1] = As[r + g + 8][kk + tig];
                af[mf][2] = As[r + g][kk + tig + 4];
                af[mf][3] = As[r + g + 8][kk + tig + 4];
            }
#pragma unroll
            for (int nf = 0; nf < 4; ++nf) {
                const int c = wn * 32 + nf * 8 + g;
                if (!BT) {
                    bf[nf][0] = Bsm[(kk + tig) * 72 + c];
                    bf[nf][1] = Bsm[(kk + tig + 4) * 72 + c];
                } else {
                    bf[nf][0] = Bsm[c * 36 + kk + tig];
                    bf[nf][1] = Bsm[c * 36 + kk + tig + 4];
                }
            }
#pragma unroll
            for (int mf = 0; mf < 2; ++mf)
#pragma unroll
                for (int nf = 0; nf < 4; ++nf)
                    mma8(acc[mf][nf], af[mf], bf[nf]);
        }
        __syncthreads();
    }

    const size_t zoff = (size_t)blockIdx.z * M * N;
#pragma unroll
    for (int mf = 0; mf < 2; ++mf)
#pragma unroll
        for (int nf = 0; nf < 4; ++nf) {
            const int row0 = bm0 + wm * 32 + mf * 16 + g;
            const int col  = bn0 + wn * 32 + nf * 8 + tig * 2;
#pragma unroll
            for (int h = 0; h < 2; ++h) {
                float2 o2 = make_float2(acc[mf][nf][h * 2], acc[mf][nf][h * 2 + 1]);
                *(float2*)(Cpart + zoff + (size_t)(row0 + h * 8) * N + col) = o2;
            }
        }
}

// reduce split-K partials + bias/relu/residual
__global__ __launch_bounds__(256) void gemm_reduce(
    const float* __restrict__ part, float* __restrict__ C, int MN, int N,
    int SK, const float* __restrict__ bias, int relu,
    const float* __restrict__ resid)
{
    const int i = blockIdx.x * 256 + threadIdx.x;
    if (i >= MN) return;
    float s = 0.f;
    for (int z = 0; z < SK; ++z) s += part[(size_t)z * MN + i];
    if (bias) s += bias[i % N];
    if (relu) s = fmaxf(s, 0.f);
    if (resid) s += resid[i];
    C[i] = s;
}

// -------------------- dots + softmax-over-slots + rowsum --------------------
__global__ __launch_bounds__(256) void dots_kernel(
    const float* __restrict__ q, const float* __restrict__ kv,
    float* __restrict__ attn, float* __restrict__ rowsum)
{
    const int b = blockIdx.y;
    __shared__ float4 qsm[kS * kD / 4];   // 16 KB
    const int tid = threadIdx.x;
    const float4* qg = (const float4*)(q + (size_t)b * kS * kD);
#pragma unroll
    for (int i = 0; i < 4; ++i) qsm[tid + i * 256] = qg[tid + i * 256];
    __syncthreads();

    const int w = tid >> 5, lane = tid & 31;
    const int f = blockIdx.x * 8 + w;
    const float4* kr = (const float4*)(kv + ((size_t)b * kF + f) * kKV);
    float acc[8];
#pragma unroll
    for (int s = 0; s < 8; ++s) acc[s] = 0.f;
#pragma unroll
    for (int c = 0; c < 4; ++c) {
        const float4 kv4 = kr[lane + c * 32];
#pragma unroll
        for (int s = 0; s < 8; ++s) {
            const float4 qv = qsm[s * 128 + lane + c * 32];
            acc[s] += kv4.x * qv.x + kv4.y * qv.y + kv4.z * qv.z + kv4.w * qv.w;
        }
    }
#pragma unroll
    for (int s = 0; s < 8; ++s)
#pragma unroll
        for (int o = 16; o; o >>= 1)
            acc[s] += __shfl_xor_sync(0xffffffffu, acc[s], o);

    float mx = -1e30f;
#pragma unroll
    for (int s = 0; s < 8; ++s) mx = fmaxf(mx, acc[s] * kSCALE);
    float e[8], tot = 0.f;
#pragma unroll
    for (int s = 0; s < 8; ++s) { e[s] = __expf(acc[s] * kSCALE - mx); tot += e[s]; }
    const float inv = 1.f / tot;

    __shared__ float psum[8][9];
    if (lane < 8) {
        const float p = e[lane] * inv;
        attn[(size_t)b * kS * kF + (size_t)lane * kF + f] = p;
        psum[lane][w] = p;
    }
    __syncthreads();
    if (tid < 8) {
        float t = 0.f;
#pragma unroll
        for (int w2 = 0; w2 < 8; ++w2) t += psum[tid][w2];
        atomicAdd(&rowsum[b * kS + tid], t);
    }
}

// -------------------- updates = attn_norm @ values (partials) ---------------
__global__ __launch_bounds__(256) void upd_kernel(
    const float* __restrict__ attn, const float* __restrict__ kv,
    const float* __restrict__ rowsum, float* __restrict__ upart)
{
    const int b = blockIdx.y, chunk = blockIdx.x;
    const int tid = threadIdx.x;
    __shared__ float wsm[8][64];
    __shared__ float inv[8];
    if (tid < 8) inv[tid] = 1.f / (rowsum[b * kS + tid] + (float)kF * kEPS);

    float acc[8][2];
#pragma unroll
    for (int s = 0; s < 8; ++s) { acc[s][0] = 0.f; acc[s][1] = 0.f; }
    float vs0 = 0.f, vs1 = 0.f;
    const int f0 = chunk * 512;
    const int d0 = tid * 2;
    const size_t abase = (size_t)b * kS * kF;

    for (int ft = 0; ft < 512; ft += 64) {
        __syncthreads();
        {
            int idx = tid;
            wsm[idx >> 6][idx & 63] = attn[abase + (size_t)(idx >> 6) * kF + f0 + ft + (idx & 63)];
            idx = tid + 256;
            wsm[idx >> 6][idx & 63] = attn[abase + (size_t)(idx >> 6) * kF + f0 + ft + (idx & 63)];
        }
        __syncthreads();
#pragma unroll 4
        for (int j = 0; j < 64; ++j) {
            const int f = f0 + ft + j;
            const float2 v = *(const float2*)(kv + ((size_t)b * kF + f) * kKV + kD + d0);
            vs0 += v.x; vs1 += v.y;
#pragma unroll
            for (int s = 0; s < 8; ++s) {
                const float wv = wsm[s][j];
                acc[s][0] += wv * v.x;
                acc[s][1] += wv * v.y;
            }
        }
    }
#pragma unroll
    for (int s = 0; s < 8; ++s) {
        const float iv = inv[s];
        const size_t o = ((size_t)(chunk * kBS + b * kS + s)) * kD + d0;
        upart[o]     = (acc[s][0] + kEPS * vs0) * iv;
        upart[o + 1] = (acc[s][1] + kEPS * vs1) * iv;
    }
}

__global__ __launch_bounds__(128) void upd_reduce(
    const float* __restrict__ upart, float* __restrict__ updates)
{
    const int bs = blockIdx.x, tid = threadIdx.x;
    float4 a = make_float4(0.f, 0.f, 0.f, 0.f);
#pragma unroll
    for (int c = 0; c < 8; ++c) {
        const float4 v = *(const float4*)(upart + ((size_t)(c * kBS + bs)) * kD + tid * 4);
        a.x += v.x; a.y += v.y; a.z += v.z; a.w += v.w;
    }
    *(float4*)(updates + (size_t)bs * kD + tid * 4) = a;
}

// -------------------- GRU gate combine ---------------------------------------
__global__ __launch_bounds__(256) void gru_kernel(
    const float* __restrict__ gi, const float* __restrict__ gh,
    const float* __restrict__ hprev, float* __restrict__ out)
{
    const int i = blockIdx.x * 256 + threadIdx.x;
    const int bs = i >> 9, d = i & 511;
    const size_t base = (size_t)bs * (3 * kD) + d;
    const float ir = gi[base], iz = gi[base + kD], in_ = gi[base + 2 * kD];
    const float hr = gh[base], hz = gh[base + kD], hn  = gh[base + 2 * kD];
    const float r = 1.f / (1.f + __expf(-(ir + hr)));
    const float z = 1.f / (1.f + __expf(-(iz + hz)));
    const float n = tanhf(in_ + r * hn);
    out[i] = (1.f - z) * n + z * hprev[i];
}

// -------------------- utility kernels ----------------------------------------
__global__ void zero_kernel(float* p, int n) {
    const int i = blockIdx.x * blockDim.x + threadIdx.x;
    if (i < n) p[i] = 0.f;
}
__global__ void copy4_kernel(float4* __restrict__ dst, const float4* __restrict__ src, int n4) {
    const int i = blockIdx.x * blockDim.x + threadIdx.x;
    if (i < n4) dst[i] = src[i];
}
__global__ void pack_wkv_kernel(const float* __restrict__ wk,
                                const float* __restrict__ wv,
                                float* __restrict__ wkv)
{
    const int i = blockIdx.x * 256 + threadIdx.x;   // kD * kKV
    const int k = i >> 10, c = i & 1023;
    wkv[i] = (c < kD) ? wk[k * kD + c] : wv[k * kD + c - kD];
}

// -------------------- host launcher ------------------------------------------
extern "C" void kernel_launch(void* const* d_in, const int* in_sizes, int n_in,
                              void* d_out, int out_size)
{
    const float* slots_in  = (const float*)d_in[0];
    const float* features  = (const float*)d_in[1];
    const float* w_k       = (const float*)d_in[2];
    const float* w_v       = (const float*)d_in[3];
    const float* w_q       = (const float*)d_in[4];
    const float* ln_feat_w = (const float*)d_in[5];
    const float* ln_feat_b = (const float*)d_in[6];
    const float* ln_slot_w = (const float*)d_in[7];
    const float* ln_slot_b = (const float*)d_in[8];
    const float* gru_w_ih  = (const float*)d_in[9];
    const float* gru_w_hh  = (const float*)d_in[10];
    const float* gru_b_ih  = (const float*)d_in[11];
    const float* gru_b_hh  = (const float*)d_in[12];
    const float* ln_mlp_w  = (const float*)d_in[13];
    const float* ln_mlp_b  = (const float*)d_in[14];
    const float* mlp_w1    = (const float*)d_in[15];
    const float* mlp_b1    = (const float*)d_in[16];
    const float* mlp_w2    = (const float*)d_in[17];
    const float* mlp_b2    = (const float*)d_in[18];

    float* out  = (float*)d_out;
    float* attn = out + kBS * kD;

    float *fln, *kv, *wkv, *sn, *q, *updates, *upart, *gi, *gh,
          *slots, *tbuf, *h1, *rowsum, *part;
    cudaGetSymbolAddress((void**)&fln,     g_fln);
    cudaGetSymbolAddress((void**)&kv,      g_kv);
    cudaGetSymbolAddress((void**)&wkv,     g_wkv);
    cudaGetSymbolAddress((void**)&sn,      g_sn);
    cudaGetSymbolAddress((void**)&q,       g_q);
    cudaGetSymbolAddress((void**)&updates, g_updates);
    cudaGetSymbolAddress((void**)&upart,   g_upart);
    cudaGetSymbolAddress((void**)&gi,      g_gi);
    cudaGetSymbolAddress((void**)&gh,      g_gh);
    cudaGetSymbolAddress((void**)&slots,   g_slots);
    cudaGetSymbolAddress((void**)&tbuf,    g_tbuf);
    cudaGetSymbolAddress((void**)&h1,      g_h1);
    cudaGetSymbolAddress((void**)&rowsum,  g_rowsum);
    cudaGetSymbolAddress((void**)&part,    g_part);

    const int big_smem = 2 * (ASZ + BSZ) * 4;   // 71680 B
    cudaFuncSetAttribute(gemm_big, cudaFuncAttributeMaxDynamicSharedMemorySize, big_smem);

    // prologue
    copy4_kernel<<<(kBS * kD / 4 + 255) / 256, 256>>>((float4*)slots, (const float4*)slots_in, kBS * kD / 4);
    pack_wkv_kernel<<<kD * kKV / 256, 256>>>(w_k, w_v, wkv);
    ln_kernel<<<kBF, 128>>>(features, ln_feat_w, ln_feat_b, fln);
    gemm_big<<<dim3(kKV / GBN, kBF / GBM), 256, big_smem>>>(fln, wkv, kv, kBF, kKV, kD);

    for (int it = 0; it < 3; ++it) {
        ln_kernel<<<kBS, 128>>>(slots, ln_slot_w, ln_slot_b, sn);

        // q = sn @ w_q : M=256,N=512,K=512, SK=8
        gemm_small<0><<<dim3(4, 8, 8), 128>>>(sn, w_q, part, kBS, kD, kD, 64);
        gemm_reduce<<<(kBS * kD + 255) / 256, 256>>>(part, q, kBS * kD, kD, 8, nullptr, 0, nullptr);

        zero_kernel<<<1, 256>>>(rowsum, kBS);
        dots_kernel<<<dim3(kF / 8, kB), 256>>>(q, kv, attn, rowsum);
        upd_kernel<<<dim3(8, kB), 256>>>(attn, kv, rowsum, upart);
        upd_reduce<<<kBS, 128>>>(upart, updates);

        // gi = updates @ gru_w_ih^T : M=256,N=1536,K=512, SK=4
        gemm_small<1><<<dim3(4, 24, 4), 128>>>(updates, gru_w_ih, part, kBS, 3 * kD, kD, 128);
        gemm_reduce<<<(kBS * 3 * kD + 255) / 256, 256>>>(part, gi, kBS * 3 * kD, 3 * kD, 4, gru_b_ih, 0, nullptr);
        // gh = sn @ gru_w_hh^T
        gemm_small<1><<<dim3(4, 24, 4), 128>>>(sn, gru_w_hh, part, kBS, 3 * kD, kD, 128);
        gemm_reduce<<<(kBS * 3 * kD + 255) / 256, 256>>>(part, gh, kBS * 3 * kD, 3 * kD, 4, gru_b_hh, 0, nullptr);

        gru_kernel<<<kBS * kD / 256, 256>>>(gi, gh, sn, slots);

        ln_kernel<<<kBS, 128>>>(slots, ln_mlp_w, ln_mlp_b, tbuf);
        // h1 = relu(tbuf @ mlp_w1 + b1) : M=256,N=2048,K=512, SK=2
        gemm_small<0><<<dim3(4, 32, 2), 128>>>(tbuf, mlp_w1, part, kBS, kH, kD, 256);
        gemm_reduce<<<(kBS * kH + 255) / 256, 256>>>(part, h1, kBS * kH, kH, 2, mlp_b1, 1, nullptr);
        // slots += h1 @ mlp_w2 + b2 : M=256,N=512,K=2048, SK=8
        gemm_small<0><<<dim3(4, 8, 8), 128>>>(h1, mlp_w2, part, kBS, kD, kH, 256);
        gemm_reduce<<<(kBS * kD + 255) / 256, 256>>>(part, slots, kBS * kD, kD, 8, mlp_b2, 0, slots);
    }

    copy4_kernel<<<(kBS * kD / 4 + 255) / 256, 256>>>((float4*)out, (const float4*)slots, kBS * kD / 4);
}

// round 13
// speedup vs baseline: 2.4969x; 1.7248x over previous
#include <cuda_runtime.h>
#include <math.h>

// ---------------------------------------------------------------------------
// SlotAttention on GB300 — round 3: algebraic elimination of K/V projections.
//   dots   = s_n @ (W_q W_k^T) @ fln^T
//   gi     = (attn_norm @ fln) @ (W_v W_ih^T) + b_ih
// B=32, F=4096, S=8, D=512, H=2048, 3 iterations.
// d_out layout: [0 : 256*512) slots, [256*512 : +32*8*4096) pre_norm_attn.
// ---------------------------------------------------------------------------

namespace {
constexpr int kB = 32, kF = 4096, kS = 8, kD = 512, kH = 2048;
constexpr int kBS = kB * kS;       // 256
constexpr int kBF = kB * kF;       // 131072
constexpr float kEPS   = 1e-8f;
constexpr float kLNEPS = 1e-5f;
constexpr float kSCALE = 0.04419417382415922f;  // D^-0.5
}

// ------------------------------ scratch (no cudaMalloc allowed) -------------
__device__ float g_fln[(size_t)kBF * kD];     // LN(features)   268 MB
__device__ float g_wqk[kD * kD];              // W_q @ W_k^T
__device__ float g_wvih[kD * 3 * kD];         // W_v @ W_ih^T
__device__ float g_sn[kBS * kD];
__device__ float g_q[kBS * kD];
__device__ float g_attnf[kBS * kD];           // attn_norm @ fln
__device__ float g_upart[8 * kBS * kD];
__device__ float g_dpart[(kF / 8) * kBS];     // rowsum partials
__device__ float g_gi[kBS * 3 * kD];
__device__ float g_gh[kBS * 3 * kD];
__device__ float g_slots[kBS * kD];
__device__ float g_tbuf[kBS * kD];
__device__ float g_h1[kBS * kH];
__device__ float g_rowsum[kBS];
__device__ float g_part[2 * 1024 * 1024];     // split-K partials 8 MB

// ------------------------------ LayerNorm (row length 512) ------------------
__global__ __launch_bounds__(128) void ln_kernel(
    const float* __restrict__ x, const float* __restrict__ w,
    const float* __restrict__ b, float* __restrict__ y)
{
    const int row = blockIdx.x;
    const int tid = threadIdx.x;
    const float4 v = ((const float4*)(x + (size_t)row * kD))[tid];
    float s  = v.x + v.y + v.z + v.w;
    float sq = v.x * v.x + v.y * v.y + v.z * v.z + v.w * v.w;
    const int lane = tid & 31, wid = tid >> 5;
#pragma unroll
    for (int o = 16; o; o >>= 1) {
        s  += __shfl_xor_sync(0xffffffffu, s, o);
        sq += __shfl_xor_sync(0xffffffffu, sq, o);
    }
    __shared__ float rs[4], rq[4];
    if (lane == 0) { rs[wid] = s; rq[wid] = sq; }
    __syncthreads();
    const float st = rs[0] + rs[1] + rs[2] + rs[3];
    const float qt = rq[0] + rq[1] + rq[2] + rq[3];
    const float m = st * (1.0f / kD);
    const float var = qt * (1.0f / kD) - m * m;
    const float rstd = rsqrtf(var + kLNEPS);
    const float4 wv = ((const float4*)w)[tid];
    const float4 bv = ((const float4*)b)[tid];
    float4 o4;
    o4.x = (v.x - m) * rstd * wv.x + bv.x;
    o4.y = (v.y - m) * rstd * wv.y + bv.y;
    o4.z = (v.z - m) * rstd * wv.z + bv.z;
    o4.w = (v.w - m) * rstd * wv.w + bv.w;
    ((float4*)(y + (size_t)row * kD))[tid] = o4;
}

// ------------------------------ tf32 helpers --------------------------------
__device__ __forceinline__ unsigned f2tf(float x) {
    unsigned r;
    asm("cvt.rna.tf32.f32 %0, %1;" : "=r"(r) : "f"(x));
    return r;
}
__device__ __forceinline__ uint4 f2tf4(float4 v) {
    uint4 t; t.x = f2tf(v.x); t.y = f2tf(v.y); t.z = f2tf(v.z); t.w = f2tf(v.w);
    return t;
}
__device__ __forceinline__ void mma8(float c[4], const unsigned a[4], const unsigned b[2]) {
    asm volatile(
        "mma.sync.aligned.m16n8k8.row.col.f32.tf32.tf32.f32 "
        "{%0,%1,%2,%3}, {%4,%5,%6,%7}, {%8,%9}, {%0,%1,%2,%3};\n"
        : "+f"(c[0]), "+f"(c[1]), "+f"(c[2]), "+f"(c[3])
        : "r"(a[0]), "r"(a[1]), "r"(a[2]), "r"(a[3]), "r"(b[0]), "r"(b[1]));
}

// ------------------------------ small split-K GEMM ---------------------------
// 64x64x32 tile, 128 threads (2x2 warps, warp tile 32x32).
// Grid (M/64, N/64, SK); each z computes Kc=K/SK and writes partials.
// BT=1: B stored [N,K] (C = A @ B^T).
template <int BT>
__global__ __launch_bounds__(128) void gemm_small(
    const float* __restrict__ A, const float* __restrict__ Bmat,
    float* __restrict__ Cpart, int M, int N, int K, int Kc)
{
    __shared__ unsigned As[64][36];
    __shared__ unsigned Bsm[2304];   // !BT: [32][72]; BT: [64][36]
    const int bm0 = blockIdx.x * 64;
    const int bn0 = blockIdx.y * 64;
    const int tid = threadIdx.x;
    const int lane = tid & 31, wid = tid >> 5;
    const int wm = wid >> 1, wn = wid & 1;
    const int g = lane >> 2, tig = lane & 3;

    float acc[2][4][4];
#pragma unroll
    for (int i = 0; i < 2; ++i)
#pragma unroll
        for (int j = 0; j < 4; ++j)
#pragma unroll
            for (int l = 0; l < 4; ++l) acc[i][j][l] = 0.0f;

    const int kbeg = blockIdx.z * Kc;
    for (int k0 = kbeg; k0 < kbeg + Kc; k0 += 32) {
#pragma unroll
        for (int i = 0; i < 4; ++i) {
            const int qq = tid + i * 128;
            const int row = qq >> 3, kc = (qq & 7) << 2;
            const float4 v = *(const float4*)(A + (size_t)(bm0 + row) * K + k0 + kc);
            *(uint4*)&As[row][kc] = f2tf4(v);
        }
        if (!BT) {
#pragma unroll
            for (int i = 0; i < 4; ++i) {
                const int qq = tid + i * 128;
                const int r = qq >> 4, c = (qq & 15) << 2;
                const float4 v = *(const float4*)(Bmat + (size_t)(k0 + r) * N + bn0 + c);
                *(uint4*)&Bsm[r * 72 + c] = f2tf4(v);
            }
        } else {
#pragma unroll
            for (int i = 0; i < 4; ++i) {
                const int qq = tid + i * 128;
                const int n = qq >> 3, kc = (qq & 7) << 2;
                const float4 v = *(const float4*)(Bmat + (size_t)(bn0 + n) * K + k0 + kc);
                *(uint4*)&Bsm[n * 36 + kc] = f2tf4(v);
            }
        }
        __syncthreads();
#pragma unroll
        for (int kk = 0; kk < 32; kk += 8) {
            unsigned af[2][4], bf[4][2];
#pragma unroll
            for (int mf = 0; mf < 2; ++mf) {
                const int r = wm * 32 + mf * 16;
                af[mf][0] = As[r + g][kk + tig];
                af[mf][1] = As[r + g + 8][kk + tig];
                af[mf][2] = As[r + g][kk + tig + 4];
                af[mf][3] = As[r + g + 8][kk + tig + 4];
            }
#pragma unroll
            for (int nf = 0; nf < 4; ++nf) {
                const int c = wn * 32 + nf * 8 + g;
                if (!BT) {
                    bf[nf][0] = Bsm[(kk + tig) * 72 + c];
                    bf[nf][1] = Bsm[(kk + tig + 4) * 72 + c];
                } else {
                    bf[nf][0] = Bsm[c * 36 + kk + tig];
                    bf[nf][1] = Bsm[c * 36 + kk + tig + 4];
                }
            }
#pragma unroll
            for (int mf = 0; mf < 2; ++mf)
#pragma unroll
                for (int nf = 0; nf < 4; ++nf)
                    mma8(acc[mf][nf], af[mf], bf[nf]);
        }
        __syncthreads();
    }

    const size_t zoff = (size_t)blockIdx.z * M * N;
#pragma unroll
    for (int mf = 0; mf < 2; ++mf)
#pragma unroll
        for (int nf = 0; nf < 4; ++nf) {
            const int row0 = bm0 + wm * 32 + mf * 16 + g;
            const int col  = bn0 + wn * 32 + nf * 8 + tig * 2;
#pragma unroll
            for (int h = 0; h < 2; ++h) {
                float2 o2 = make_float2(acc[mf][nf][h * 2], acc[mf][nf][h * 2 + 1]);
                *(float2*)(Cpart + zoff + (size_t)(row0 + h * 8) * N + col) = o2;
            }
        }
}

// reduce split-K partials + bias/relu/residual
__global__ __launch_bounds__(256) void gemm_reduce(
    const float* __restrict__ part, float* __restrict__ C, int MN, int N,
    int SK, const float* __restrict__ bias, int relu,
    const float* __restrict__ resid)
{
    const int i = blockIdx.x * 256 + threadIdx.x;
    if (i >= MN) return;
    float s = 0.f;
    for (int z = 0; z < SK; ++z) s += part[(size_t)z * MN + i];
    if (bias) s += bias[i % N];
    if (relu) s = fmaxf(s, 0.f);
    if (resid) s += resid[i];
    C[i] = s;
}

// -------------------- dots + softmax-over-slots + rowsum partials -----------
// grid (F/8, B), block 256: one warp per f; q[b] cached in smem; reads fln.
__global__ __launch_bounds__(256) void dots_kernel(
    const float* __restrict__ q, const float* __restrict__ fln,
    float* __restrict__ attn, float* __restrict__ dpart)
{
    const int b = blockIdx.y;
    __shared__ float4 qsm[kS * kD / 4];   // 16 KB
    const int tid = threadIdx.x;
    const float4* qg = (const float4*)(q + (size_t)b * kS * kD);
#pragma unroll
    for (int i = 0; i < 4; ++i) qsm[tid + i * 256] = qg[tid + i * 256];
    __syncthreads();

    const int w = tid >> 5, lane = tid & 31;
    const int f = blockIdx.x * 8 + w;
    const float4* kr = (const float4*)(fln + ((size_t)b * kF + f) * kD);
    float acc[8];
#pragma unroll
    for (int s = 0; s < 8; ++s) acc[s] = 0.f;
#pragma unroll
    for (int c = 0; c < 4; ++c) {
        const float4 kv4 = kr[lane + c * 32];
#pragma unroll
        for (int s = 0; s < 8; ++s) {
            const float4 qv = qsm[s * 128 + lane + c * 32];
            acc[s] += kv4.x * qv.x + kv4.y * qv.y + kv4.z * qv.z + kv4.w * qv.w;
        }
    }
#pragma unroll
    for (int s = 0; s < 8; ++s)
#pragma unroll
        for (int o = 16; o; o >>= 1)
            acc[s] += __shfl_xor_sync(0xffffffffu, acc[s], o);

    float mx = -1e30f;
#pragma unroll
    for (int s = 0; s < 8; ++s) mx = fmaxf(mx, acc[s] * kSCALE);
    float e[8], tot = 0.f;
#pragma unroll
    for (int s = 0; s < 8; ++s) { e[s] = __expf(acc[s] * kSCALE - mx); tot += e[s]; }
    const float inv = 1.f / tot;

    __shared__ float psum[8][9];
    if (lane < 8) {
        const float p = e[lane] * inv;
        attn[(size_t)b * kS * kF + (size_t)lane * kF + f] = p;
        psum[lane][w] = p;
    }
    __syncthreads();
    if (tid < 8) {
        float t = 0.f;
#pragma unroll
        for (int w2 = 0; w2 < 8; ++w2) t += psum[tid][w2];
        dpart[(size_t)blockIdx.x * kBS + b * kS + tid] = t;   // deterministic
    }
}

// deterministic rowsum reduce: rowsum[bs] = sum_c dpart[c][bs]
__global__ __launch_bounds__(256) void rowsum_kernel(
    const float* __restrict__ dpart, float* __restrict__ rowsum)
{
    const int bs = threadIdx.x;
    float s = 0.f;
#pragma unroll 8
    for (int c = 0; c < kF / 8; ++c) s += dpart[(size_t)c * kBS + bs];
    rowsum[bs] = s;
}

// -------------------- attnf = attn_norm @ fln (partials) --------------------
__global__ __launch_bounds__(256) void upd_kernel(
    const float* __restrict__ attn, const float* __restrict__ fln,
    const float* __restrict__ rowsum, float* __restrict__ upart)
{
    const int b = blockIdx.y, chunk = blockIdx.x;
    const int tid = threadIdx.x;
    __shared__ float wsm[8][64];
    __shared__ float inv[8];
    if (tid < 8) inv[tid] = 1.f / (rowsum[b * kS + tid] + (float)kF * kEPS);

    float acc[8][2];
#pragma unroll
    for (int s = 0; s < 8; ++s) { acc[s][0] = 0.f; acc[s][1] = 0.f; }
    float vs0 = 0.f, vs1 = 0.f;
    const int f0 = chunk * 512;
    const int d0 = tid * 2;
    const size_t abase = (size_t)b * kS * kF;

    for (int ft = 0; ft < 512; ft += 64) {
        __syncthreads();
        {
            int idx = tid;
            wsm[idx >> 6][idx & 63] = attn[abase + (size_t)(idx >> 6) * kF + f0 + ft + (idx & 63)];
            idx = tid + 256;
            wsm[idx >> 6][idx & 63] = attn[abase + (size_t)(idx >> 6) * kF + f0 + ft + (idx & 63)];
        }
        __syncthreads();
#pragma unroll 4
        for (int j = 0; j < 64; ++j) {
            const int f = f0 + ft + j;
            const float2 v = *(const float2*)(fln + ((size_t)b * kF + f) * kD + d0);
            vs0 += v.x; vs1 += v.y;
#pragma unroll
            for (int s = 0; s < 8; ++s) {
                const float wv = wsm[s][j];
                acc[s][0] += wv * v.x;
                acc[s][1] += wv * v.y;
            }
        }
    }
#pragma unroll
    for (int s = 0; s < 8; ++s) {
        const float iv = inv[s];
        const size_t o = ((size_t)(chunk * kBS + b * kS + s)) * kD + d0;
        upart[o]     = (acc[s][0] + kEPS * vs0) * iv;
        upart[o + 1] = (acc[s][1] + kEPS * vs1) * iv;
    }
}

__global__ __launch_bounds__(128) void upd_reduce(
    const float* __restrict__ upart, float* __restrict__ attnf)
{
    const int bs = blockIdx.x, tid = threadIdx.x;
    float4 a = make_float4(0.f, 0.f, 0.f, 0.f);
#pragma unroll
    for (int c = 0; c < 8; ++c) {
        const float4 v = *(const float4*)(upart + ((size_t)(c * kBS + bs)) * kD + tid * 4);
        a.x += v.x; a.y += v.y; a.z += v.z; a.w += v.w;
    }
    *(float4*)(attnf + (size_t)bs * kD + tid * 4) = a;
}

// -------------------- GRU gate combine ---------------------------------------
__global__ __launch_bounds__(256) void gru_kernel(
    const float* __restrict__ gi, const float* __restrict__ gh,
    const float* __restrict__ hprev, float* __restrict__ out)
{
    const int i = blockIdx.x * 256 + threadIdx.x;
    const int bs = i >> 9, d = i & 511;
    const size_t base = (size_t)bs * (3 * kD) + d;
    const float ir = gi[base], iz = gi[base + kD], in_ = gi[base + 2 * kD];
    const float hr = gh[base], hz = gh[base + kD], hn  = gh[base + 2 * kD];
    const float r = 1.f / (1.f + __expf(-(ir + hr)));
    const float z = 1.f / (1.f + __expf(-(iz + hz)));
    const float n = tanhf(in_ + r * hn);
    out[i] = (1.f - z) * n + z * hprev[i];
}

// -------------------- utility ------------------------------------------------
__global__ void copy4_kernel(float4* __restrict__ dst, const float4* __restrict__ src, int n4) {
    const int i = blockIdx.x * blockDim.x + threadIdx.x;
    if (i < n4) dst[i] = src[i];
}

// -------------------- host launcher ------------------------------------------
extern "C" void kernel_launch(void* const* d_in, const int* in_sizes, int n_in,
                              void* d_out, int out_size)
{
    const float* slots_in  = (const float*)d_in[0];
    const float* features  = (const float*)d_in[1];
    const float* w_k       = (const float*)d_in[2];
    const float* w_v       = (const float*)d_in[3];
    const float* w_q       = (const float*)d_in[4];
    const float* ln_feat_w = (const float*)d_in[5];
    const float* ln_feat_b = (const float*)d_in[6];
    const float* ln_slot_w = (const float*)d_in[7];
    const float* ln_slot_b = (const float*)d_in[8];
    const float* gru_w_ih  = (const float*)d_in[9];
    const float* gru_w_hh  = (const float*)d_in[10];
    const float* gru_b_ih  = (const float*)d_in[11];
    const float* gru_b_hh  = (const float*)d_in[12];
    const float* ln_mlp_w  = (const float*)d_in[13];
    const float* ln_mlp_b  = (const float*)d_in[14];
    const float* mlp_w1    = (const float*)d_in[15];
    const float* mlp_b1    = (const float*)d_in[16];
    const float* mlp_w2    = (const float*)d_in[17];
    const float* mlp_b2    = (const float*)d_in[18];

    float* out  = (float*)d_out;
    float* attn = out + kBS * kD;

    float *fln, *wqk, *wvih, *sn, *q, *attnf, *upart, *dpart, *gi, *gh,
          *slots, *tbuf, *h1, *rowsum, *part;
    cudaGetSymbolAddress((void**)&fln,    g_fln);
    cudaGetSymbolAddress((void**)&wqk,    g_wqk);
    cudaGetSymbolAddress((void**)&wvih,   g_wvih);
    cudaGetSymbolAddress((void**)&sn,     g_sn);
    cudaGetSymbolAddress((void**)&q,      g_q);
    cudaGetSymbolAddress((void**)&attnf,  g_attnf);
    cudaGetSymbolAddress((void**)&upart,  g_upart);
    cudaGetSymbolAddress((void**)&dpart,  g_dpart);
    cudaGetSymbolAddress((void**)&gi,     g_gi);
    cudaGetSymbolAddress((void**)&gh,     g_gh);
    cudaGetSymbolAddress((void**)&slots,  g_slots);
    cudaGetSymbolAddress((void**)&tbuf,   g_tbuf);
    cudaGetSymbolAddress((void**)&h1,     g_h1);
    cudaGetSymbolAddress((void**)&rowsum, g_rowsum);
    cudaGetSymbolAddress((void**)&part,   g_part);

    // ---- prologue ----
    copy4_kernel<<<(kBS * kD / 4 + 255) / 256, 256>>>((float4*)slots, (const float4*)slots_in, kBS * kD / 4);
    ln_kernel<<<kBF, 128>>>(features, ln_feat_w, ln_feat_b, fln);

    // wqk = w_q @ w_k^T : M=512, N=512, K=512
    gemm_small<1><<<dim3(8, 8, 2), 128>>>(w_q, w_k, part, kD, kD, kD, 256);
    gemm_reduce<<<(kD * kD + 255) / 256, 256>>>(part, wqk, kD * kD, kD, 2, nullptr, 0, nullptr);
    // wvih = w_v @ gru_w_ih^T : M=512, N=1536, K=512
    gemm_small<1><<<dim3(8, 24, 2), 128>>>(w_v, gru_w_ih, part, kD, 3 * kD, kD, 256);
    gemm_reduce<<<(kD * 3 * kD + 255) / 256, 256>>>(part, wvih, kD * 3 * kD, 3 * kD, 2, nullptr, 0, nullptr);

    for (int it = 0; it < 3; ++it) {
        ln_kernel<<<kBS, 128>>>(slots, ln_slot_w, ln_slot_b, sn);

        // q' = sn @ wqk : M=256, N=512, K=512
        gemm_small<0><<<dim3(4, 8, 8), 128>>>(sn, wqk, part, kBS, kD, kD, 64);
        gemm_reduce<<<(kBS * kD + 255) / 256, 256>>>(part, q, kBS * kD, kD, 8, nullptr, 0, nullptr);

        dots_kernel<<<dim3(kF / 8, kB), 256>>>(q, fln, attn, dpart);
        rowsum_kernel<<<1, kBS>>>(dpart, rowsum);
        upd_kernel<<<dim3(8, kB), 256>>>(attn, fln, rowsum, upart);
        upd_reduce<<<kBS, 128>>>(upart, attnf);

        // gi = attnf @ wvih + b_ih : M=256, N=1536, K=512
        gemm_small<0><<<dim3(4, 24, 4), 128>>>(attnf, wvih, part, kBS, 3 * kD, kD, 128);
        gemm_reduce<<<(kBS * 3 * kD + 255) / 256, 256>>>(part, gi, kBS * 3 * kD, 3 * kD, 4, gru_b_ih, 0, nullptr);
        // gh = sn @ gru_w_hh^T + b_hh
        gemm_small<1><<<dim3(4, 24, 4), 128>>>(sn, gru_w_hh, part, kBS, 3 * kD, kD, 128);
        gemm_reduce<<<(kBS * 3 * kD + 255) / 256, 256>>>(part, gh, kBS * 3 * kD, 3 * kD, 4, gru_b_hh, 0, nullptr);

        gru_kernel<<<kBS * kD / 256, 256>>>(gi, gh, sn, slots);

        ln_kernel<<<kBS, 128>>>(slots, ln_mlp_w, ln_mlp_b, tbuf);
        // h1 = relu(tbuf @ mlp_w1 + b1) : M=256, N=2048, K=512
        gemm_small<0><<<dim3(4, 32, 2), 128>>>(tbuf, mlp_w1, part, kBS, kH, kD, 256);
        gemm_reduce<<<(kBS * kH + 255) / 256, 256>>>(part, h1, kBS * kH, kH, 2, mlp_b1, 1, nullptr);
        // slots += h1 @ mlp_w2 + b2 : M=256, N=512, K=2048
        gemm_small<0><<<dim3(4, 8, 8), 128>>>(h1, mlp_w2, part, kBS, kD, kH, 256);
        gemm_reduce<<<(kBS * kD + 255) / 256, 256>>>(part, slots, kBS * kD, kD, 8, mlp_b2, 0, slots);
    }

    copy4_kernel<<<(kBS * kD / 4 + 255) / 256, 256>>>((float4*)out, (const float4*)slots, kBS * kD / 4);
}

// round 14
// speedup vs baseline: 2.9808x; 1.1938x over previous
#include <cuda_runtime.h>
#include <math.h>

// ---------------------------------------------------------------------------
// SlotAttention on GB300 — round 4:
//  * fused LN(features)+dots+softmax+update streaming kernel (features read 1x/iter)
//  * fused GRU+LN and MLP2-reduce+residual+LN kernels (9 launches/iter)
//  * algebraic elimination of K/V projections (wqk = Wq Wk^T, wvih = Wv Wih^T)
// d_out layout: [0 : 256*512) slots, [256*512 : +32*8*4096) pre_norm_attn.
// ---------------------------------------------------------------------------

namespace {
constexpr int kB = 32, kF = 4096, kS = 8, kD = 512, kH = 2048;
constexpr int kBS = kB * kS;       // 256
constexpr float kEPS   = 1e-8f;
constexpr float kLNEPS = 1e-5f;
constexpr float kSCALE = 0.04419417382415922f;  // D^-0.5
}

// ------------------------------ scratch (no cudaMalloc allowed) -------------
__device__ float g_wqk[kD * kD];              // W_q @ W_k^T
__device__ float g_wvih[kD * 3 * kD];         // W_v @ W_ih^T
__device__ float g_whht[kD * 3 * kD];         // W_hh^T (pre-transposed)
__device__ float g_sn[kBS * kD];
__device__ float g_q[kBS * kD];
__device__ float g_attnf[kBS * kD];
__device__ float g_upart[8 * kBS * kD];       // update numerator partials
__device__ float g_dpart[8 * kBS];            // rowsum partials
__device__ float g_slots[kBS * kD];
__device__ float g_tbuf[kBS * kD];
__device__ float g_h1[kBS * kH];
__device__ float g_part[4 * 1024 * 1024];     // split-K partials (16 MB)

// ------------------------------ LayerNorm (row length 512) ------------------
__global__ __launch_bounds__(128) void ln_kernel(
    const float* __restrict__ x, const float* __restrict__ w,
    const float* __restrict__ b, float* __restrict__ y)
{
    const int row = blockIdx.x;
    const int tid = threadIdx.x;
    const float4 v = ((const float4*)(x + (size_t)row * kD))[tid];
    float s  = v.x + v.y + v.z + v.w;
    float sq = v.x * v.x + v.y * v.y + v.z * v.z + v.w * v.w;
    const int lane = tid & 31, wid = tid >> 5;
#pragma unroll
    for (int o = 16; o; o >>= 1) {
        s  += __shfl_xor_sync(0xffffffffu, s, o);
        sq += __shfl_xor_sync(0xffffffffu, sq, o);
    }
    __shared__ float rs[4], rq[4];
    if (lane == 0) { rs[wid] = s; rq[wid] = sq; }
    __syncthreads();
    const float st = rs[0] + rs[1] + rs[2] + rs[3];
    const float qt = rq[0] + rq[1] + rq[2] + rq[3];
    const float m = st * (1.0f / kD);
    const float var = qt * (1.0f / kD) - m * m;
    const float rstd = rsqrtf(var + kLNEPS);
    const float4 wv = ((const float4*)w)[tid];
    const float4 bv = ((const float4*)b)[tid];
    float4 o4;
    o4.x = (v.x - m) * rstd * wv.x + bv.x;
    o4.y = (v.y - m) * rstd * wv.y + bv.y;
    o4.z = (v.z - m) * rstd * wv.z + bv.z;
    o4.w = (v.w - m) * rstd * wv.w + bv.w;
    ((float4*)(y + (size_t)row * kD))[tid] = o4;
}

// shared 128-thread block LN (each thread holds 4 consecutive elems of a 512 row)
__device__ __forceinline__ float4 block_ln_128(float4 v, float4 wv, float4 bv)
{
    float s  = v.x + v.y + v.z + v.w;
    float sq = v.x * v.x + v.y * v.y + v.z * v.z + v.w * v.w;
    const int lane = threadIdx.x & 31, wid = threadIdx.x >> 5;
#pragma unroll
    for (int o = 16; o; o >>= 1) {
        s  += __shfl_xor_sync(0xffffffffu, s, o);
        sq += __shfl_xor_sync(0xffffffffu, sq, o);
    }
    __shared__ float rs[4], rq[4];
    if (lane == 0) { rs[wid] = s; rq[wid] = sq; }
    __syncthreads();
    const float st = rs[0] + rs[1] + rs[2] + rs[3];
    const float qt = rq[0] + rq[1] + rq[2] + rq[3];
    const float m = st * (1.0f / kD);
    const float var = qt * (1.0f / kD) - m * m;
    const float rstd = rsqrtf(var + kLNEPS);
    float4 o;
    o.x = (v.x - m) * rstd * wv.x + bv.x;
    o.y = (v.y - m) * rstd * wv.y + bv.y;
    o.z = (v.z - m) * rstd * wv.z + bv.z;
    o.w = (v.w - m) * rstd * wv.w + bv.w;
    return o;
}

// ------------------------------ tf32 helpers --------------------------------
__device__ __forceinline__ unsigned f2tf(float x) {
    unsigned r;
    asm("cvt.rna.tf32.f32 %0, %1;" : "=r"(r) : "f"(x));
    return r;
}
__device__ __forceinline__ uint4 f2tf4(float4 v) {
    uint4 t; t.x = f2tf(v.x); t.y = f2tf(v.y); t.z = f2tf(v.z); t.w = f2tf(v.w);
    return t;
}
__device__ __forceinline__ void mma8(float c[4], const unsigned a[4], const unsigned b[2]) {
    asm volatile(
        "mma.sync.aligned.m16n8k8.row.col.f32.tf32.tf32.f32 "
        "{%0,%1,%2,%3}, {%4,%5,%6,%7}, {%8,%9}, {%0,%1,%2,%3};\n"
        : "+f"(c[0]), "+f"(c[1]), "+f"(c[2]), "+f"(c[3])
        : "r"(a[0]), "r"(a[1]), "r"(a[2]), "r"(a[3]), "r"(b[0]), "r"(b[1]));
}

// ------------------------------ small split-K GEMM ---------------------------
// 64x64x32 tile, 128 threads. Grid (M/64, N/64, SK); z writes partial at z*M*N.
// SK==1 (Kc==K) => direct full result at Cpart. BT=1: C = A @ B^T.
template <int BT>
__global__ __launch_bounds__(128) void gemm_small(
    const float* __restrict__ A, const float* __restrict__ Bmat,
    float* __restrict__ Cpart, int M, int N, int K, int Kc)
{
    __shared__ unsigned As[64][36];
    __shared__ unsigned Bsm[2304];
    const int bm0 = blockIdx.x * 64;
    const int bn0 = blockIdx.y * 64;
    const int tid = threadIdx.x;
    const int lane = tid & 31, wid = tid >> 5;
    const int wm = wid >> 1, wn = wid & 1;
    const int g = lane >> 2, tig = lane & 3;

    float acc[2][4][4];
#pragma unroll
    for (int i = 0; i < 2; ++i)
#pragma unroll
        for (int j = 0; j < 4; ++j)
#pragma unroll
            for (int l = 0; l < 4; ++l) acc[i][j][l] = 0.0f;

    const int kbeg = blockIdx.z * Kc;
    for (int k0 = kbeg; k0 < kbeg + Kc; k0 += 32) {
#pragma unroll
        for (int i = 0; i < 4; ++i) {
            const int qq = tid + i * 128;
            const int row = qq >> 3, kc = (qq & 7) << 2;
            const float4 v = *(const float4*)(A + (size_t)(bm0 + row) * K + k0 + kc);
            *(uint4*)&As[row][kc] = f2tf4(v);
        }
        if (!BT) {
#pragma unroll
            for (int i = 0; i < 4; ++i) {
                const int qq = tid + i * 128;
                const int r = qq >> 4, c = (qq & 15) << 2;
                const float4 v = *(const float4*)(Bmat + (size_t)(k0 + r) * N + bn0 + c);
                *(uint4*)&Bsm[r * 72 + c] = f2tf4(v);
            }
        } else {
#pragma unroll
            for (int i = 0; i < 4; ++i) {
                const int qq = tid + i * 128;
                const int n = qq >> 3, kc = (qq & 7) << 2;
                const float4 v = *(const float4*)(Bmat + (size_t)(bn0 + n) * K + k0 + kc);
                *(uint4*)&Bsm[n * 36 + kc] = f2tf4(v);
            }
        }
        __syncthreads();
#pragma unroll
        for (int kk = 0; kk < 32; kk += 8) {
            unsigned af[2][4], bf[4][2];
#pragma unroll
            for (int mf = 0; mf < 2; ++mf) {
                const int r = wm * 32 + mf * 16;
                af[mf][0] = As[r + g][kk + tig];
                af[mf][1] = As[r + g + 8][kk + tig];
                af[mf][2] = As[r + g][kk + tig + 4];
                af[mf][3] = As[r + g + 8][kk + tig + 4];
            }
#pragma unroll
            for (int nf = 0; nf < 4; ++nf) {
                const int c = wn * 32 + nf * 8 + g;
                if (!BT) {
                    bf[nf][0] = Bsm[(kk + tig) * 72 + c];
                    bf[nf][1] = Bsm[(kk + tig + 4) * 72 + c];
                } else {
                    bf[nf][0] = Bsm[c * 36 + kk + tig];
                    bf[nf][1] = Bsm[c * 36 + kk + tig + 4];
                }
            }
#pragma unroll
            for (int mf = 0; mf < 2; ++mf)
#pragma unroll
                for (int nf = 0; nf < 4; ++nf)
                    mma8(acc[mf][nf], af[mf], bf[nf]);
        }
        __syncthreads();
    }

    const size_t zoff = (size_t)blockIdx.z * M * N;
#pragma unroll
    for (int mf = 0; mf < 2; ++mf)
#pragma unroll
        for (int nf = 0; nf < 4; ++nf) {
            const int row0 = bm0 + wm * 32 + mf * 16 + g;
            const int col  = bn0 + wn * 32 + nf * 8 + tig * 2;
#pragma unroll
            for (int h = 0; h < 2; ++h) {
                float2 o2 = make_float2(acc[mf][nf][h * 2], acc[mf][nf][h * 2 + 1]);
                *(float2*)(Cpart + zoff + (size_t)(row0 + h * 8) * N + col) = o2;
            }
        }
}

// reduce split-K partials + bias/relu (used for MLP1 only)
__global__ __launch_bounds__(256) void gemm_reduce(
    const float* __restrict__ part, float* __restrict__ C, int MN, int N,
    int SK, const float* __restrict__ bias, int relu)
{
    const int i = blockIdx.x * 256 + threadIdx.x;
    if (i >= MN) return;
    float s = 0.f;
    for (int z = 0; z < SK; ++z) s += part[(size_t)z * MN + i];
    if (bias) s += bias[i % N];
    if (relu) s = fmaxf(s, 0.f);
    C[i] = s;
}

// -------------------- fused LN + dots + softmax + update --------------------
// grid (8 f-chunks, 32 b), block 256 (8 warps). Streams 16-row feature tiles
// through smem (double buffered, register prefetch). LN applied in place.
// Writes attn (pre_norm softmax over slots), update numerator partials,
// and per-chunk rowsum partials (normalization deferred to attn_finish).
#define FA_SMEM ((4096 + 512 + 512 + 16384 + 128) * 4)

__global__ __launch_bounds__(256) void fused_attn(
    const float* __restrict__ q, const float* __restrict__ features,
    const float* __restrict__ lnw, const float* __restrict__ lnb,
    float* __restrict__ attn, float* __restrict__ upart,
    float* __restrict__ dpart)
{
    extern __shared__ float sm[];
    float* qsm  = sm;                    // 4096 floats
    float* lws  = sm + 4096;             // 512
    float* lbs  = sm + 4608;             // 512
    float* tile = sm + 5120;             // 2 x 8192
    float* wsm  = sm + 5120 + 16384;     // 8 x 16

    const int b = blockIdx.y, chunk = blockIdx.x;
    const int tid = threadIdx.x, w = tid >> 5, lane = tid & 31;

    {
        const float4* qg = (const float4*)(q + (size_t)b * kS * kD);
        float4* q4 = (float4*)qsm;
#pragma unroll
        for (int i = 0; i < 4; ++i) q4[tid + i * 256] = qg[tid + i * 256];
    }
    if (tid < 128)       ((float4*)lws)[tid]       = ((const float4*)lnw)[tid];
    else                 ((float4*)lbs)[tid - 128] = ((const float4*)lnb)[tid - 128];

    const float* fbase = features + ((size_t)b * kF + chunk * 512) * kD;
    {
        const float4* fg = (const float4*)fbase;
        float4* t4 = (float4*)tile;
#pragma unroll
        for (int i = 0; i < 8; ++i) t4[tid + i * 256] = fg[tid + i * 256];
    }
    __syncthreads();

    float acc[8][2];
#pragma unroll
    for (int s = 0; s < 8; ++s) { acc[s][0] = 0.f; acc[s][1] = 0.f; }
    float vs0 = 0.f, vs1 = 0.f, rs = 0.f;
    const int d0 = tid * 2;
    int cur = 0;
    float4 pf[8];
    const float4* q4 = (const float4*)qsm;
    const float4* lw4 = (const float4*)lws;
    const float4* lb4 = (const float4*)lbs;

    for (int t = 0; t < 32; ++t) {
        if (t < 31) {
            const float4* fg = (const float4*)(fbase + (size_t)(t + 1) * 8192);
#pragma unroll
            for (int i = 0; i < 8; ++i) pf[i] = fg[tid + i * 256];
        }
        float* tl = tile + cur * 8192;

        // ---- dots phase: in-place LN of 2 rows per warp, dot vs q, softmax ----
#pragma unroll
        for (int rr = 0; rr < 2; ++rr) {
            const int r = w * 2 + rr;
            float4 kv[4];
            float s1 = 0.f, s2 = 0.f;
#pragma unroll
            for (int c = 0; c < 4; ++c) {
                kv[c] = *(float4*)(tl + r * 512 + (lane + c * 32) * 4);
                s1 += kv[c].x + kv[c].y + kv[c].z + kv[c].w;
                s2 += kv[c].x * kv[c].x + kv[c].y * kv[c].y
                    + kv[c].z * kv[c].z + kv[c].w * kv[c].w;
            }
#pragma unroll
            for (int o = 16; o; o >>= 1) {
                s1 += __shfl_xor_sync(0xffffffffu, s1, o);
                s2 += __shfl_xor_sync(0xffffffffu, s2, o);
            }
            const float m = s1 * (1.0f / kD);
            const float var = s2 * (1.0f / kD) - m * m;
            const float rstd = rsqrtf(var + kLNEPS);

            float a8[8];
#pragma unroll
            for (int s = 0; s < 8; ++s) a8[s] = 0.f;
#pragma unroll
            for (int c = 0; c < 4; ++c) {
                const float4 wv = lw4[lane + c * 32];
                const float4 bv = lb4[lane + c * 32];
                float4 nv;
                nv.x = (kv[c].x - m) * rstd * wv.x + bv.x;
                nv.y = (kv[c].y - m) * rstd * wv.y + bv.y;
                nv.z = (kv[c].z - m) * rstd * wv.z + bv.z;
                nv.w = (kv[c].w - m) * rstd * wv.w + bv.w;
                *(float4*)(tl + r * 512 + (lane + c * 32) * 4) = nv;
#pragma unroll
                for (int s = 0; s < 8; ++s) {
                    const float4 qv = q4[s * 128 + lane + c * 32];
                    a8[s] += nv.x * qv.x + nv.y * qv.y + nv.z * qv.z + nv.w * qv.w;
                }
            }
#pragma unroll
            for (int s = 0; s < 8; ++s)
#pragma unroll
                for (int o = 16; o; o >>= 1)
                    a8[s] += __shfl_xor_sync(0xffffffffu, a8[s], o);

            float mx = -1e30f;
#pragma unroll
            for (int s = 0; s < 8; ++s) mx = fmaxf(mx, a8[s] * kSCALE);
            float e[8], tot = 0.f;
#pragma unroll
            for (int s = 0; s < 8; ++s) { e[s] = __expf(a8[s] * kSCALE - mx); tot += e[s]; }
            const float inv = 1.f / tot;
            if (lane < 8) {
                const float p = e[lane] * inv;
                attn[(size_t)(b * 8 + lane) * kF + chunk * 512 + t * 16 + r] = p;
                wsm[lane * 16 + r] = p;
            }
        }
        __syncthreads();

        // ---- update phase: accumulate p*v and sum(v) from normalized tile ----
#pragma unroll 4
        for (int j = 0; j < 16; ++j) {
            const float2 v = *(const float2*)(tl + j * 512 + d0);
            vs0 += v.x; vs1 += v.y;
#pragma unroll
            for (int s = 0; s < 8; ++s) {
                const float wv = wsm[s * 16 + j];
                acc[s][0] += wv * v.x;
                acc[s][1] += wv * v.y;
            }
        }
        if (tid < 8) {
            float tt = 0.f;
#pragma unroll
            for (int j = 0; j < 16; ++j) tt += wsm[tid * 16 + j];
            rs += tt;
        }
        if (t < 31) {
            float4* t4 = (float4*)(tile + (cur ^ 1) * 8192);
#pragma unroll
            for (int i = 0; i < 8; ++i) t4[tid + i * 256] = pf[i];
        }
        __syncthreads();
        cur ^= 1;
    }

#pragma unroll
    for (int s = 0; s < 8; ++s) {
        const size_t o = ((size_t)(chunk * kBS + b * 8 + s)) * kD + d0;
        upart[o]     = acc[s][0] + kEPS * vs0;
        upart[o + 1] = acc[s][1] + kEPS * vs1;
    }
    if (tid < 8) dpart[chunk * kBS + b * 8 + tid] = rs;
}

// finish: attnf[bs] = sum_chunk upart / (rowsum + F*eps)
__global__ __launch_bounds__(128) void attn_finish(
    const float* __restrict__ upart, const float* __restrict__ dpart,
    float* __restrict__ attnf)
{
    const int bs = blockIdx.x, tid = threadIdx.x;
    __shared__ float invs;
    if (tid == 0) {
        float r = 0.f;
#pragma unroll
        for (int c = 0; c < 8; ++c) r += dpart[c * kBS + bs];
        invs = 1.f / (r + (float)kF * kEPS);
    }
    __syncthreads();
    float4 a = make_float4(0.f, 0.f, 0.f, 0.f);
#pragma unroll
    for (int c = 0; c < 8; ++c) {
        const float4 v = ((const float4*)(upart + ((size_t)(c * kBS + bs)) * kD))[tid];
        a.x += v.x; a.y += v.y; a.z += v.z; a.w += v.w;
    }
    const float iv = invs;
    a.x *= iv; a.y *= iv; a.z *= iv; a.w *= iv;
    ((float4*)(attnf + (size_t)bs * kD))[tid] = a;
}

// -------------------- fused GRU (from partials) + LN_mlp ---------------------
__global__ __launch_bounds__(128) void gru_ln_kernel(
    const float* __restrict__ part,     // gi partials z=0..3, gh partials z=4..7
    const float* __restrict__ b_ih, const float* __restrict__ b_hh,
    const float* __restrict__ sn,
    const float* __restrict__ lnw, const float* __restrict__ lnb,
    float* __restrict__ slots, float* __restrict__ tbuf)
{
    const int row = blockIdx.x, tid = threadIdx.x;
    const int d0 = tid * 4;
    const size_t MNg = (size_t)kBS * 3 * kD;

    float4 gir = make_float4(0,0,0,0), giz = gir, gin = gir;
    float4 ghr = gir, ghz = gir, ghn = gir;
#pragma unroll
    for (int z = 0; z < 4; ++z) {
        const float* p  = part + z * MNg + (size_t)row * 3 * kD;
        const float* p2 = part + (4 + z) * MNg + (size_t)row * 3 * kD;
        float4 v;
        v = *(const float4*)(p + d0);            gir.x+=v.x; gir.y+=v.y; gir.z+=v.z; gir.w+=v.w;
        v = *(const float4*)(p + kD + d0);       giz.x+=v.x; giz.y+=v.y; giz.z+=v.z; giz.w+=v.w;
        v = *(const float4*)(p + 2*kD + d0);     gin.x+=v.x; gin.y+=v.y; gin.z+=v.z; gin.w+=v.w;
        v = *(const float4*)(p2 + d0);           ghr.x+=v.x; ghr.y+=v.y; ghr.z+=v.z; ghr.w+=v.w;
        v = *(const float4*)(p2 + kD + d0);      ghz.x+=v.x; ghz.y+=v.y; ghz.z+=v.z; ghz.w+=v.w;
        v = *(const float4*)(p2 + 2*kD + d0);    ghn.x+=v.x; ghn.y+=v.y; ghn.z+=v.z; ghn.w+=v.w;
    }
    {
        float4 v;
        v = *(const float4*)(b_ih + d0);         gir.x+=v.x; gir.y+=v.y; gir.z+=v.z; gir.w+=v.w;
        v = *(const float4*)(b_ih + kD + d0);    giz.x+=v.x; giz.y+=v.y; giz.z+=v.z; giz.w+=v.w;
        v = *(const float4*)(b_ih + 2*kD + d0);  gin.x+=v.x; gin.y+=v.y; gin.z+=v.z; gin.w+=v.w;
        v = *(const float4*)(b_hh + d0);         ghr.x+=v.x; ghr.y+=v.y; ghr.z+=v.z; ghr.w+=v.w;
        v = *(const float4*)(b_hh + kD + d0);    ghz.x+=v.x; ghz.y+=v.y; ghz.z+=v.z; ghz.w+=v.w;
        v = *(const float4*)(b_hh + 2*kD + d0);  ghn.x+=v.x; ghn.y+=v.y; ghn.z+=v.z; ghn.w+=v.w;
    }
    const float4 hp = *(const float4*)(sn + (size_t)row * kD + d0);

    float4 h;
    {
        float r, zz, n;
        r = 1.f/(1.f+__expf(-(gir.x+ghr.x))); zz = 1.f/(1.f+__expf(-(giz.x+ghz.x)));
        n = tanhf(gin.x + r*ghn.x); h.x = (1.f-zz)*n + zz*hp.x;
        r = 1.f/(1.f+__expf(-(gir.y+ghr.y))); zz = 1.f/(1.f+__expf(-(giz.y+ghz.y)));
        n = tanhf(gin.y + r*ghn.y); h.y = (1.f-zz)*n + zz*hp.y;
        r = 1.f/(1.f+__expf(-(gir.z+ghr.z))); zz = 1.f/(1.f+__expf(-(giz.z+ghz.z)));
        n = tanhf(gin.z + r*ghn.z); h.z = (1.f-zz)*n + zz*hp.z;
        r = 1.f/(1.f+__expf(-(gir.w+ghr.w))); zz = 1.f/(1.f+__expf(-(giz.w+ghz.w)));
        n = tanhf(gin.w + r*ghn.w); h.w = (1.f-zz)*n + zz*hp.w;
    }
    *(float4*)(slots + (size_t)row * kD + d0) = h;

    const float4 wv = *(const float4*)(lnw + d0);
    const float4 bv = *(const float4*)(lnb + d0);
    const float4 o = block_ln_128(h, wv, bv);
    *(float4*)(tbuf + (size_t)row * kD + d0) = o;
}

// -------------------- MLP2 reduce + bias + residual + LN_slot ---------------
__global__ __launch_bounds__(128) void mlp2_ln_kernel(
    const float* __restrict__ part, const float* __restrict__ bias,
    const float* __restrict__ lnw, const float* __restrict__ lnb,
    float* __restrict__ slots, float* __restrict__ sn)
{
    const int row = blockIdx.x, tid = threadIdx.x;
    const int d0 = tid * 4;
    const size_t MN2 = (size_t)kBS * kD;
    float4 a = make_float4(0.f, 0.f, 0.f, 0.f);
#pragma unroll
    for (int z = 0; z < 8; ++z) {
        const float4 v = *(const float4*)(part + z * MN2 + (size_t)row * kD + d0);
        a.x += v.x; a.y += v.y; a.z += v.z; a.w += v.w;
    }
    {
        const float4 bb = *(const float4*)(bias + d0);
        const float4 rr = *(const float4*)(slots + (size_t)row * kD + d0);
        a.x += bb.x + rr.x; a.y += bb.y + rr.y;
        a.z += bb.z + rr.z; a.w += bb.w + rr.w;
    }
    *(float4*)(slots + (size_t)row * kD + d0) = a;

    const float4 wv = *(const float4*)(lnw + d0);
    const float4 bv = *(const float4*)(lnb + d0);
    const float4 o = block_ln_128(a, wv, bv);
    *(float4*)(sn + (size_t)row * kD + d0) = o;
}

// -------------------- utility ------------------------------------------------
__global__ void copy4_kernel(float4* __restrict__ dst, const float4* __restrict__ src, int n4) {
    const int i = blockIdx.x * blockDim.x + threadIdx.x;
    if (i < n4) dst[i] = src[i];
}
// transpose [1536,512] -> [512,1536]
__global__ __launch_bounds__(256) void transpose_kernel(
    const float* __restrict__ in, float* __restrict__ out)
{
    __shared__ float t[32][33];
    const int tx = threadIdx.x & 31, ty = threadIdx.x >> 5;  // 32x8
    const int c0 = blockIdx.x * 32;   // col of in (512)
    const int r0 = blockIdx.y * 32;   // row of in (1536)
#pragma unroll
    for (int i = 0; i < 4; ++i)
        t[ty + i * 8][tx] = in[(size_t)(r0 + ty + i * 8) * 512 + c0 + tx];
    __syncthreads();
#pragma unroll
    for (int i = 0; i < 4; ++i)
        out[(size_t)(c0 + ty + i * 8) * 1536 + r0 + tx] = t[tx][ty + i * 8];
}

// -------------------- host launcher ------------------------------------------
extern "C" void kernel_launch(void* const* d_in, const int* in_sizes, int n_in,
                              void* d_out, int out_size)
{
    const float* slots_in  = (const float*)d_in[0];
    const float* features  = (const float*)d_in[1];
    const float* w_k       = (const float*)d_in[2];
    const float* w_v       = (const float*)d_in[3];
    const float* w_q       = (const float*)d_in[4];
    const float* ln_feat_w = (const float*)d_in[5];
    const float* ln_feat_b = (const float*)d_in[6];
    const float* ln_slot_w = (const float*)d_in[7];
    const float* ln_slot_b = (const float*)d_in[8];
    const float* gru_w_ih  = (const float*)d_in[9];
    const float* gru_w_hh  = (const float*)d_in[10];
    const float* gru_b_ih  = (const float*)d_in[11];
    const float* gru_b_hh  = (const float*)d_in[12];
    const float* ln_mlp_w  = (const float*)d_in[13];
    const float* ln_mlp_b  = (const float*)d_in[14];
    const float* mlp_w1    = (const float*)d_in[15];
    const float* mlp_b1    = (const float*)d_in[16];
    const float* mlp_w2    = (const float*)d_in[17];
    const float* mlp_b2    = (const float*)d_in[18];

    float* out  = (float*)d_out;
    float* attn = out + kBS * kD;

    float *wqk, *wvih, *whht, *sn, *q, *attnf, *upart, *dpart,
          *slots, *tbuf, *h1, *part;
    cudaGetSymbolAddress((void**)&wqk,   g_wqk);
    cudaGetSymbolAddress((void**)&wvih,  g_wvih);
    cudaGetSymbolAddress((void**)&whht,  g_whht);
    cudaGetSymbolAddress((void**)&sn,    g_sn);
    cudaGetSymbolAddress((void**)&q,     g_q);
    cudaGetSymbolAddress((void**)&attnf, g_attnf);
    cudaGetSymbolAddress((void**)&upart, g_upart);
    cudaGetSymbolAddress((void**)&dpart, g_dpart);
    cudaGetSymbolAddress((void**)&slots, g_slots);
    cudaGetSymbolAddress((void**)&tbuf,  g_tbuf);
    cudaGetSymbolAddress((void**)&h1,    g_h1);
    cudaGetSymbolAddress((void**)&part,  g_part);

    cudaFuncSetAttribute(fused_attn, cudaFuncAttributeMaxDynamicSharedMemorySize, FA_SMEM);

    const size_t MNg = (size_t)kBS * 3 * kD;

    // ---- prologue ----
    copy4_kernel<<<(kBS * kD / 4 + 255) / 256, 256>>>((float4*)slots, (const float4*)slots_in, kBS * kD / 4);
    ln_kernel<<<kBS, 128>>>(slots, ln_slot_w, ln_slot_b, sn);
    transpose_kernel<<<dim3(16, 48), 256>>>(gru_w_hh, whht);
    // wqk = w_q @ w_k^T (direct)
    gemm_small<1><<<dim3(8, 8, 1), 128>>>(w_q, w_k, wqk, kD, kD, kD, kD);
    // wvih = w_v @ gru_w_ih^T (direct)
    gemm_small<1><<<dim3(8, 24, 1), 128>>>(w_v, gru_w_ih, wvih, kD, 3 * kD, kD, kD);

    for (int it = 0; it < 3; ++it) {
        // q = sn @ wqk (direct)
        gemm_small<0><<<dim3(4, 8, 1), 128>>>(sn, wqk, q, kBS, kD, kD, kD);
        // fused LN(features) + dots + softmax + update numerators
        fused_attn<<<dim3(8, kB), 256, FA_SMEM>>>(q, features, ln_feat_w, ln_feat_b,
                                                  attn, upart, dpart);
        attn_finish<<<kBS, 128>>>(upart, dpart, attnf);
        // gi partials (z=0..3), gh partials (z=4..7)
        gemm_small<0><<<dim3(4, 24, 4), 128>>>(attnf, wvih, part, kBS, 3 * kD, kD, 128);
        gemm_small<0><<<dim3(4, 24, 4), 128>>>(sn, whht, part + 4 * MNg, kBS, 3 * kD, kD, 128);
        // GRU from partials + LN_mlp
        gru_ln_kernel<<<kBS, 128>>>(part, gru_b_ih, gru_b_hh, sn,
                                    ln_mlp_w, ln_mlp_b, slots, tbuf);
        // h1 = relu(tbuf @ mlp_w1 + b1), split-K 2
        gemm_small<0><<<dim3(4, 32, 2), 128>>>(tbuf, mlp_w1, part, kBS, kH, kD, 256);
        gemm_reduce<<<(kBS * kH + 255) / 256, 256>>>(part, h1, kBS * kH, kH, 2, mlp_b1, 1);
        // mlp2 partials, split-K 8; then reduce + bias + residual + LN_slot -> sn
        gemm_small<0><<<dim3(4, 8, 8), 128>>>(h1, mlp_w2, part, kBS, kD, kH, 256);
        mlp2_ln_kernel<<<kBS, 128>>>(part, mlp_b2, ln_slot_w, ln_slot_b, slots, sn);
    }

    copy4_kernel<<<(kBS * kD / 4 + 255) / 256, 256>>>((float4*)out, (const float4*)slots, kBS * kD / 4);
}

// round 15
// speedup vs baseline: 3.4774x; 1.1666x over previous
#include <cuda_runtime.h>
#include <math.h>

// ---------------------------------------------------------------------------
// SlotAttention on GB300 — round 5:
//  * pipelined split-K small GEMMs (latency-tolerant, SK=8/16 everywhere)
//  * q split-K reduce folded into fused_attn; gate/mlp2 reduces folded into
//    gru_ln / mlp2_ln epilogue kernels
//  * fused LN(features)+dots+softmax+update streaming kernel (features 1x/iter)
//  * algebraic elimination of K/V projections (wqk = Wq Wk^T, wvih = Wv Wih^T)
// d_out layout: [0 : 256*512) slots, [256*512 : +32*8*4096) pre_norm_attn.
// ---------------------------------------------------------------------------

namespace {
constexpr int kB = 32, kF = 4096, kS = 8, kD = 512, kH = 2048;
constexpr int kBS = kB * kS;       // 256
constexpr float kEPS   = 1e-8f;
constexpr float kLNEPS = 1e-5f;
constexpr float kSCALE = 0.04419417382415922f;  // D^-0.5
}

// ------------------------------ scratch (no cudaMalloc allowed) -------------
__device__ float g_wqk[kD * kD];              // W_q @ W_k^T
__device__ float g_wvih[kD * 3 * kD];         // W_v @ W_ih^T
__device__ float g_whht[kD * 3 * kD];         // W_hh^T (pre-transposed)
__device__ float g_sn[kBS * kD];
__device__ float g_attnf[kBS * kD];
__device__ float g_upart[8 * kBS * kD];       // update numerator partials
__device__ float g_dpart[8 * kBS];            // rowsum partials
__device__ float g_slots[kBS * kD];
__device__ float g_tbuf[kBS * kD];
__device__ float g_h1[kBS * kH];
__device__ float g_part[8 * 1024 * 1024];     // split-K partials (32 MB)

// ------------------------------ LayerNorm (row length 512) ------------------
__global__ __launch_bounds__(128) void ln_kernel(
    const float* __restrict__ x, const float* __restrict__ w,
    const float* __restrict__ b, float* __restrict__ y)
{
    const int row = blockIdx.x;
    const int tid = threadIdx.x;
    const float4 v = ((const float4*)(x + (size_t)row * kD))[tid];
    float s  = v.x + v.y + v.z + v.w;
    float sq = v.x * v.x + v.y * v.y + v.z * v.z + v.w * v.w;
    const int lane = tid & 31, wid = tid >> 5;
#pragma unroll
    for (int o = 16; o; o >>= 1) {
        s  += __shfl_xor_sync(0xffffffffu, s, o);
        sq += __shfl_xor_sync(0xffffffffu, sq, o);
    }
    __shared__ float rs[4], rq[4];
    if (lane == 0) { rs[wid] = s; rq[wid] = sq; }
    __syncthreads();
    const float st = rs[0] + rs[1] + rs[2] + rs[3];
    const float qt = rq[0] + rq[1] + rq[2] + rq[3];
    const float m = st * (1.0f / kD);
    const float var = qt * (1.0f / kD) - m * m;
    const float rstd = rsqrtf(var + kLNEPS);
    const float4 wv = ((const float4*)w)[tid];
    const float4 bv = ((const float4*)b)[tid];
    float4 o4;
    o4.x = (v.x - m) * rstd * wv.x + bv.x;
    o4.y = (v.y - m) * rstd * wv.y + bv.y;
    o4.z = (v.z - m) * rstd * wv.z + bv.z;
    o4.w = (v.w - m) * rstd * wv.w + bv.w;
    ((float4*)(y + (size_t)row * kD))[tid] = o4;
}

// shared 128-thread block LN helper (thread holds 4 consecutive elems)
__device__ __forceinline__ float4 block_ln_128(float4 v, float4 wv, float4 bv)
{
    float s  = v.x + v.y + v.z + v.w;
    float sq = v.x * v.x + v.y * v.y + v.z * v.z + v.w * v.w;
    const int lane = threadIdx.x & 31, wid = threadIdx.x >> 5;
#pragma unroll
    for (int o = 16; o; o >>= 1) {
        s  += __shfl_xor_sync(0xffffffffu, s, o);
        sq += __shfl_xor_sync(0xffffffffu, sq, o);
    }
    __shared__ float rs[4], rq[4];
    if (lane == 0) { rs[wid] = s; rq[wid] = sq; }
    __syncthreads();
    const float st = rs[0] + rs[1] + rs[2] + rs[3];
    const float qt = rq[0] + rq[1] + rq[2] + rq[3];
    const float m = st * (1.0f / kD);
    const float var = qt * (1.0f / kD) - m * m;
    const float rstd = rsqrtf(var + kLNEPS);
    float4 o;
    o.x = (v.x - m) * rstd * wv.x + bv.x;
    o.y = (v.y - m) * rstd * wv.y + bv.y;
    o.z = (v.z - m) * rstd * wv.z + bv.z;
    o.w = (v.w - m) * rstd * wv.w + bv.w;
    return o;
}

// ------------------------------ tf32 helpers --------------------------------
__device__ __forceinline__ unsigned f2tf(float x) {
    unsigned r;
    asm("cvt.rna.tf32.f32 %0, %1;" : "=r"(r) : "f"(x));
    return r;
}
__device__ __forceinline__ uint4 f2tf4(float4 v) {
    uint4 t; t.x = f2tf(v.x); t.y = f2tf(v.y); t.z = f2tf(v.z); t.w = f2tf(v.w);
    return t;
}
__device__ __forceinline__ void mma8(float c[4], const unsigned a[4], const unsigned b[2]) {
    asm volatile(
        "mma.sync.aligned.m16n8k8.row.col.f32.tf32.tf32.f32 "
        "{%0,%1,%2,%3}, {%4,%5,%6,%7}, {%8,%9}, {%0,%1,%2,%3};\n"
        : "+f"(c[0]), "+f"(c[1]), "+f"(c[2]), "+f"(c[3])
        : "r"(a[0]), "r"(a[1]), "r"(a[2]), "r"(a[3]), "r"(b[0]), "r"(b[1]));
}

// ------------------------------ pipelined split-K GEMM -----------------------
// 64x64x32 tile, 128 threads (2x2 warps, warp tile 32x32), double-buffered
// smem + register prefetch. Grid (M/64, N/64, SK); z writes partial at z*M*N.
// BT=1: B stored [N,K] (C = A @ B^T).
template <int BT>
__global__ __launch_bounds__(128) void gemm_small(
    const float* __restrict__ A, const float* __restrict__ Bmat,
    float* __restrict__ Cpart, int M, int N, int K, int Kc)
{
    __shared__ unsigned As[2][2304];   // [64][36]
    __shared__ unsigned Bs[2][2304];   // !BT: [32][72]; BT: [64][36]
    const int bm0 = blockIdx.x * 64;
    const int bn0 = blockIdx.y * 64;
    const int tid = threadIdx.x;
    const int lane = tid & 31, wid = tid >> 5;
    const int wm = wid >> 1, wn = wid & 1;
    const int g = lane >> 2, tig = lane & 3;

    int arow[4], akc[4], br[4], bc[4];
#pragma unroll
    for (int i = 0; i < 4; ++i) {
        const int qq = tid + i * 128;
        arow[i] = qq >> 3;  akc[i] = (qq & 7) << 2;
        if (!BT) { br[i] = qq >> 4; bc[i] = (qq & 15) << 2; }
        else     { br[i] = qq >> 3; bc[i] = (qq & 7) << 2; }
    }

    float acc[2][4][4];
#pragma unroll
    for (int i = 0; i < 2; ++i)
#pragma unroll
        for (int j = 0; j < 4; ++j)
#pragma unroll
            for (int l = 0; l < 4; ++l) acc[i][j][l] = 0.0f;

    const int kbeg = blockIdx.z * Kc;
    const int kend = kbeg + Kc;

    float4 ra[4], rb[4];
#pragma unroll
    for (int i = 0; i < 4; ++i) {
        ra[i] = *(const float4*)(A + (size_t)(bm0 + arow[i]) * K + kbeg + akc[i]);
        rb[i] = BT ? *(const float4*)(Bmat + (size_t)(bn0 + br[i]) * K + kbeg + bc[i])
                   : *(const float4*)(Bmat + (size_t)(kbeg + br[i]) * N + bn0 + bc[i]);
    }
#pragma unroll
    for (int i = 0; i < 4; ++i) {
        *(uint4*)&As[0][arow[i] * 36 + akc[i]] = f2tf4(ra[i]);
        if (!BT) {
            *(uint4*)&Bs[0][br[i] * 72 + bc[i]] = f2tf4(rb[i]);
        } else {
            Bs[0][(bc[i] + 0) * 0 + br[i] * 36 + bc[i] + 0] = f2tf(rb[i].x);
            Bs[0][br[i] * 36 + bc[i] + 1] = f2tf(rb[i].y);
            Bs[0][br[i] * 36 + bc[i] + 2] = f2tf(rb[i].z);
            Bs[0][br[i] * 36 + bc[i] + 3] = f2tf(rb[i].w);
        }
    }
    __syncthreads();

    int cur = 0;
    for (int k0 = kbeg; k0 < kend; k0 += 32) {
        const int kn = k0 + 32;
        if (kn < kend) {
#pragma unroll
            for (int i = 0; i < 4; ++i) {
                ra[i] = *(const float4*)(A + (size_t)(bm0 + arow[i]) * K + kn + akc[i]);
                rb[i] = BT ? *(const float4*)(Bmat + (size_t)(bn0 + br[i]) * K + kn + bc[i])
                           : *(const float4*)(Bmat + (size_t)(kn + br[i]) * N + bn0 + bc[i]);
            }
        }
        const unsigned* Ac = As[cur];
        const unsigned* Bc = Bs[cur];
#pragma unroll
        for (int kk = 0; kk < 32; kk += 8) {
            unsigned af[2][4], bf[4][2];
#pragma unroll
            for (int mf = 0; mf < 2; ++mf) {
                const int r = wm * 32 + mf * 16;
                af[mf][0] = Ac[(r + g) * 36 + kk + tig];
                af[mf][1] = Ac[(r + g + 8) * 36 + kk + tig];
                af[mf][2] = Ac[(r + g) * 36 + kk + tig + 4];
                af[mf][3] = Ac[(r + g + 8) * 36 + kk + tig + 4];
            }
#pragma unroll
            for (int nf = 0; nf < 4; ++nf) {
                const int c = wn * 32 + nf * 8 + g;
                if (!BT) {
                    bf[nf][0] = Bc[(kk + tig) * 72 + c];
                    bf[nf][1] = Bc[(kk + tig + 4) * 72 + c];
                } else {
                    bf[nf][0] = Bc[c * 36 + kk + tig];
                    bf[nf][1] = Bc[c * 36 + kk + tig + 4];
                }
            }
#pragma unroll
            for (int mf = 0; mf < 2; ++mf)
#pragma unroll
                for (int nf = 0; nf < 4; ++nf)
                    mma8(acc[mf][nf], af[mf], bf[nf]);
        }
        if (kn < kend) {
            unsigned* An = As[cur ^ 1];
            unsigned* Bn = Bs[cur ^ 1];
#pragma unroll
            for (int i = 0; i < 4; ++i) {
                *(uint4*)&An[arow[i] * 36 + akc[i]] = f2tf4(ra[i]);
                if (!BT) {
                    *(uint4*)&Bn[br[i] * 72 + bc[i]] = f2tf4(rb[i]);
                } else {
                    Bn[br[i] * 36 + bc[i] + 0] = f2tf(rb[i].x);
                    Bn[br[i] * 36 + bc[i] + 1] = f2tf(rb[i].y);
                    Bn[br[i] * 36 + bc[i] + 2] = f2tf(rb[i].z);
                    Bn[br[i] * 36 + bc[i] + 3] = f2tf(rb[i].w);
                }
            }
        }
        __syncthreads();
        cur ^= 1;
    }

    const size_t zoff = (size_t)blockIdx.z * M * N;
#pragma unroll
    for (int mf = 0; mf < 2; ++mf)
#pragma unroll
        for (int nf = 0; nf < 4; ++nf) {
            const int row0 = bm0 + wm * 32 + mf * 16 + g;
            const int col  = bn0 + wn * 32 + nf * 8 + tig * 2;
#pragma unroll
            for (int h = 0; h < 2; ++h) {
                float2 o2 = make_float2(acc[mf][nf][h * 2], acc[mf][nf][h * 2 + 1]);
                *(float2*)(Cpart + zoff + (size_t)(row0 + h * 8) * N + col) = o2;
            }
        }
}

// reduce split-K partials + optional bias/relu
__global__ __launch_bounds__(256) void gemm_reduce(
    const float* __restrict__ part, float* __restrict__ C, int MN, int N,
    int SK, const float* __restrict__ bias, int relu)
{
    const int i = blockIdx.x * 256 + threadIdx.x;
    if (i >= MN) return;
    float s = 0.f;
    for (int z = 0; z < SK; ++z) s += part[(size_t)z * MN + i];
    if (bias) s += bias[i % N];
    if (relu) s = fmaxf(s, 0.f);
    C[i] = s;
}

// -------------------- fused LN + dots + softmax + update --------------------
// grid (8 f-chunks, 32 b), block 256. Sums SKQ=8 q partials while staging q.
#define FA_SMEM ((4096 + 512 + 512 + 16384 + 128) * 4)

__global__ __launch_bounds__(256) void fused_attn(
    const float* __restrict__ qpart, const float* __restrict__ features,
    const float* __restrict__ lnw, const float* __restrict__ lnb,
    float* __restrict__ attn, float* __restrict__ upart,
    float* __restrict__ dpart)
{
    extern __shared__ float sm[];
    float* qsm  = sm;                    // 4096 floats
    float* lws  = sm + 4096;             // 512
    float* lbs  = sm + 4608;             // 512
    float* tile = sm + 5120;             // 2 x 8192
    float* wsm  = sm + 5120 + 16384;     // 8 x 16

    const int b = blockIdx.y, chunk = blockIdx.x;
    const int tid = threadIdx.x, w = tid >> 5, lane = tid & 31;

    {   // q[b] = sum of 8 split-K partial slabs
        const float4* qp = (const float4*)qpart;
        const size_t slab = (size_t)kBS * kD / 4;
        const size_t base = (size_t)b * kS * kD / 4;
        float4* q4 = (float4*)qsm;
#pragma unroll
        for (int i = 0; i < 4; ++i) {
            const size_t idx = base + tid + i * 256;
            float4 a = qp[idx];
#pragma unroll
            for (int z = 1; z < 8; ++z) {
                const float4 v = qp[z * slab + idx];
                a.x += v.x; a.y += v.y; a.z += v.z; a.w += v.w;
            }
            q4[tid + i * 256] = a;
        }
    }
    if (tid < 128)       ((float4*)lws)[tid]       = ((const float4*)lnw)[tid];
    else                 ((float4*)lbs)[tid - 128] = ((const float4*)lnb)[tid - 128];

    const float* fbase = features + ((size_t)b * kF + chunk * 512) * kD;
    {
        const float4* fg = (const float4*)fbase;
        float4* t4 = (float4*)tile;
#pragma unroll
        for (int i = 0; i < 8; ++i) t4[tid + i * 256] = fg[tid + i * 256];
    }
    __syncthreads();

    float acc[8][2];
#pragma unroll
    for (int s = 0; s < 8; ++s) { acc[s][0] = 0.f; acc[s][1] = 0.f; }
    float vs0 = 0.f, vs1 = 0.f, rs = 0.f;
    const int d0 = tid * 2;
    int cur = 0;
    float4 pf[8];
    const float4* q4 = (const float4*)qsm;
    const float4* lw4 = (const float4*)lws;
    const float4* lb4 = (const float4*)lbs;

    for (int t = 0; t < 32; ++t) {
        if (t < 31) {
            const float4* fg = (const float4*)(fbase + (size_t)(t + 1) * 8192);
#pragma unroll
            for (int i = 0; i < 8; ++i) pf[i] = fg[tid + i * 256];
        }
        float* tl = tile + cur * 8192;

        // dots phase: in-place LN of 2 rows per warp, dot vs q, softmax
#pragma unroll
        for (int rr = 0; rr < 2; ++rr) {
            const int r = w * 2 + rr;
            float4 kv[4];
            float s1 = 0.f, s2 = 0.f;
#pragma unroll
            for (int c = 0; c < 4; ++c) {
                kv[c] = *(float4*)(tl + r * 512 + (lane + c * 32) * 4);
                s1 += kv[c].x + kv[c].y + kv[c].z + kv[c].w;
                s2 += kv[c].x * kv[c].x + kv[c].y * kv[c].y
                    + kv[c].z * kv[c].z + kv[c].w * kv[c].w;
            }
#pragma unroll
            for (int o = 16; o; o >>= 1) {
                s1 += __shfl_xor_sync(0xffffffffu, s1, o);
                s2 += __shfl_xor_sync(0xffffffffu, s2, o);
            }
            const float m = s1 * (1.0f / kD);
            const float var = s2 * (1.0f / kD) - m * m;
            const float rstd = rsqrtf(var + kLNEPS);

            float a8[8];
#pragma unroll
            for (int s = 0; s < 8; ++s) a8[s] = 0.f;
#pragma unroll
            for (int c = 0; c < 4; ++c) {
                const float4 wv = lw4[lane + c * 32];
                const float4 bv = lb4[lane + c * 32];
                float4 nv;
                nv.x = (kv[c].x - m) * rstd * wv.x + bv.x;
                nv.y = (kv[c].y - m) * rstd * wv.y + bv.y;
                nv.z = (kv[c].z - m) * rstd * wv.z + bv.z;
                nv.w = (kv[c].w - m) * rstd * wv.w + bv.w;
                *(float4*)(tl + r * 512 + (lane + c * 32) * 4) = nv;
#pragma unroll
                for (int s = 0; s < 8; ++s) {
                    const float4 qv = q4[s * 128 + lane + c * 32];
                    a8[s] += nv.x * qv.x + nv.y * qv.y + nv.z * qv.z + nv.w * qv.w;
                }
            }
#pragma unroll
            for (int s = 0; s < 8; ++s)
#pragma unroll
                for (int o = 16; o; o >>= 1)
                    a8[s] += __shfl_xor_sync(0xffffffffu, a8[s], o);

            float mx = -1e30f;
#pragma unroll
            for (int s = 0; s < 8; ++s) mx = fmaxf(mx, a8[s] * kSCALE);
            float e[8], tot = 0.f;
#pragma unroll
            for (int s = 0; s < 8; ++s) { e[s] = __expf(a8[s] * kSCALE - mx); tot += e[s]; }
            const float inv = 1.f / tot;
            if (lane < 8) {
                const float p = e[lane] * inv;
                attn[(size_t)(b * 8 + lane) * kF + chunk * 512 + t * 16 + r] = p;
                wsm[lane * 16 + r] = p;
            }
        }
        __syncthreads();

        // update phase
#pragma unroll 4
        for (int j = 0; j < 16; ++j) {
            const float2 v = *(const float2*)(tl + j * 512 + d0);
            vs0 += v.x; vs1 += v.y;
#pragma unroll
            for (int s = 0; s < 8; ++s) {
                const float wv = wsm[s * 16 + j];
                acc[s][0] += wv * v.x;
                acc[s][1] += wv * v.y;
            }
        }
        if (tid < 8) {
            float tt = 0.f;
#pragma unroll
            for (int j = 0; j < 16; ++j) tt += wsm[tid * 16 + j];
            rs += tt;
        }
        if (t < 31) {
            float4* t4 = (float4*)(tile + (cur ^ 1) * 8192);
#pragma unroll
            for (int i = 0; i < 8; ++i) t4[tid + i * 256] = pf[i];
        }
        __syncthreads();
        cur ^= 1;
    }

#pragma unroll
    for (int s = 0; s < 8; ++s) {
        const size_t o = ((size_t)(chunk * kBS + b * 8 + s)) * kD + d0;
        upart[o]     = acc[s][0] + kEPS * vs0;
        upart[o + 1] = acc[s][1] + kEPS * vs1;
    }
    if (tid < 8) dpart[chunk * kBS + b * 8 + tid] = rs;
}

// finish: attnf[bs] = sum_chunk upart / (rowsum + F*eps)
__global__ __launch_bounds__(128) void attn_finish(
    const float* __restrict__ upart, const float* __restrict__ dpart,
    float* __restrict__ attnf)
{
    const int bs = blockIdx.x, tid = threadIdx.x;
    __shared__ float invs;
    if (tid == 0) {
        float r = 0.f;
#pragma unroll
        for (int c = 0; c < 8; ++c) r += dpart[c * kBS + bs];
        invs = 1.f / (r + (float)kF * kEPS);
    }
    __syncthreads();
    float4 a = make_float4(0.f, 0.f, 0.f, 0.f);
#pragma unroll
    for (int c = 0; c < 8; ++c) {
        const float4 v = ((const float4*)(upart + ((size_t)(c * kBS + bs)) * kD))[tid];
        a.x += v.x; a.y += v.y; a.z += v.z; a.w += v.w;
    }
    const float iv = invs;
    a.x *= iv; a.y *= iv; a.z *= iv; a.w *= iv;
    ((float4*)(attnf + (size_t)bs * kD))[tid] = a;
}

// -------------------- fused GRU (from partials) + LN_mlp ---------------------
// part: gi partials z=0..7, gh partials z=8..15
__global__ __launch_bounds__(128) void gru_ln_kernel(
    const float* __restrict__ part,
    const float* __restrict__ b_ih, const float* __restrict__ b_hh,
    const float* __restrict__ sn,
    const float* __restrict__ lnw, const float* __restrict__ lnb,
    float* __restrict__ slots, float* __restrict__ tbuf)
{
    const int row = blockIdx.x, tid = threadIdx.x;
    const int d0 = tid * 4;
    const size_t MNg = (size_t)kBS * 3 * kD;

    float4 gir = make_float4(0,0,0,0), giz = gir, gin = gir;
    float4 ghr = gir, ghz = gir, ghn = gir;
#pragma unroll
    for (int z = 0; z < 8; ++z) {
        const float* p  = part + z * MNg + (size_t)row * 3 * kD;
        const float* p2 = part + (8 + z) * MNg + (size_t)row * 3 * kD;
        float4 v;
        v = *(const float4*)(p + d0);            gir.x+=v.x; gir.y+=v.y; gir.z+=v.z; gir.w+=v.w;
        v = *(const float4*)(p + kD + d0);       giz.x+=v.x; giz.y+=v.y; giz.z+=v.z; giz.w+=v.w;
        v = *(const float4*)(p + 2*kD + d0);     gin.x+=v.x; gin.y+=v.y; gin.z+=v.z; gin.w+=v.w;
        v = *(const float4*)(p2 + d0);           ghr.x+=v.x; ghr.y+=v.y; ghr.z+=v.z; ghr.w+=v.w;
        v = *(const float4*)(p2 + kD + d0);      ghz.x+=v.x; ghz.y+=v.y; ghz.z+=v.z; ghz.w+=v.w;
        v = *(const float4*)(p2 + 2*kD + d0);    ghn.x+=v.x; ghn.y+=v.y; ghn.z+=v.z; ghn.w+=v.w;
    }
    {
        float4 v;
        v = *(const float4*)(b_ih + d0);         gir.x+=v.x; gir.y+=v.y; gir.z+=v.z; gir.w+=v.w;
        v = *(const float4*)(b_ih + kD + d0);    giz.x+=v.x; giz.y+=v.y; giz.z+=v.z; giz.w+=v.w;
        v = *(const float4*)(b_ih + 2*kD + d0);  gin.x+=v.x; gin.y+=v.y; gin.z+=v.z; gin.w+=v.w;
        v = *(const float4*)(b_hh + d0);         ghr.x+=v.x; ghr.y+=v.y; ghr.z+=v.z; ghr.w+=v.w;
        v = *(const float4*)(b_hh + kD + d0);    ghz.x+=v.x; ghz.y+=v.y; ghz.z+=v.z; ghz.w+=v.w;
        v = *(const float4*)(b_hh + 2*kD + d0);  ghn.x+=v.x; ghn.y+=v.y; ghn.z+=v.z; ghn.w+=v.w;
    }
    const float4 hp = *(const float4*)(sn + (size_t)row * kD + d0);

    float4 h;
    {
        float r, zz, n;
        r = 1.f/(1.f+__expf(-(gir.x+ghr.x))); zz = 1.f/(1.f+__expf(-(giz.x+ghz.x)));
        n = tanhf(gin.x + r*ghn.x); h.x = (1.f-zz)*n + zz*hp.x;
        r = 1.f/(1.f+__expf(-(gir.y+ghr.y))); zz = 1.f/(1.f+__expf(-(giz.y+ghz.y)));
        n = tanhf(gin.y + r*ghn.y); h.y = (1.f-zz)*n + zz*hp.y;
        r = 1.f/(1.f+__expf(-(gir.z+ghr.z))); zz = 1.f/(1.f+__expf(-(giz.z+ghz.z)));
        n = tanhf(gin.z + r*ghn.z); h.z = (1.f-zz)*n + zz*hp.z;
        r = 1.f/(1.f+__expf(-(gir.w+ghr.w))); zz = 1.f/(1.f+__expf(-(giz.w+ghz.w)));
        n = tanhf(gin.w + r*ghn.w); h.w = (1.f-zz)*n + zz*hp.w;
    }
    *(float4*)(slots + (size_t)row * kD + d0) = h;

    const float4 wv = *(const float4*)(lnw + d0);
    const float4 bv = *(const float4*)(lnb + d0);
    const float4 o = block_ln_128(h, wv, bv);
    *(float4*)(tbuf + (size_t)row * kD + d0) = o;
}

// -------------------- MLP2 reduce(16) + bias + residual + LN_slot -----------
__global__ __launch_bounds__(128) void mlp2_ln_kernel(
    const float* __restrict__ part, const float* __restrict__ bias,
    const float* __restrict__ lnw, const float* __restrict__ lnb,
    float* __restrict__ slots, float* __restrict__ sn)
{
    const int row = blockIdx.x, tid = threadIdx.x;
    const int d0 = tid * 4;
    const size_t MN2 = (size_t)kBS * kD;
    float4 a = make_float4(0.f, 0.f, 0.f, 0.f);
#pragma unroll
    for (int z = 0; z < 16; ++z) {
        const float4 v = *(const float4*)(part + z * MN2 + (size_t)row * kD + d0);
        a.x += v.x; a.y += v.y; a.z += v.z; a.w += v.w;
    }
    {
        const float4 bb = *(const float4*)(bias + d0);
        const float4 rr = *(const float4*)(slots + (size_t)row * kD + d0);
        a.x += bb.x + rr.x; a.y += bb.y + rr.y;
        a.z += bb.z + rr.z; a.w += bb.w + rr.w;
    }
    *(float4*)(slots + (size_t)row * kD + d0) = a;

    const float4 wv = *(const float4*)(lnw + d0);
    const float4 bv = *(const float4*)(lnb + d0);
    const float4 o = block_ln_128(a, wv, bv);
    *(float4*)(sn + (size_t)row * kD + d0) = o;
}

// -------------------- utility ------------------------------------------------
__global__ void copy4_kernel(float4* __restrict__ dst, const float4* __restrict__ src, int n4) {
    const int i = blockIdx.x * blockDim.x + threadIdx.x;
    if (i < n4) dst[i] = src[i];
}
// transpose [1536,512] -> [512,1536]
__global__ __launch_bounds__(256) void transpose_kernel(
    const float* __restrict__ in, float* __restrict__ out)
{
    __shared__ float t[32][33];
    const int tx = threadIdx.x & 31, ty = threadIdx.x >> 5;  // 32x8
    const int c0 = blockIdx.x * 32;
    const int r0 = blockIdx.y * 32;
#pragma unroll
    for (int i = 0; i < 4; ++i)
        t[ty + i * 8][tx] = in[(size_t)(r0 + ty + i * 8) * 512 + c0 + tx];
    __syncthreads();
#pragma unroll
    for (int i = 0; i < 4; ++i)
        out[(size_t)(c0 + ty + i * 8) * 1536 + r0 + tx] = t[tx][ty + i * 8];
}

// -------------------- host launcher ------------------------------------------
extern "C" void kernel_launch(void* const* d_in, const int* in_sizes, int n_in,
                              void* d_out, int out_size)
{
    const float* slots_in  = (const float*)d_in[0];
    const float* features  = (const float*)d_in[1];
    const float* w_k       = (const float*)d_in[2];
    const float* w_v       = (const float*)d_in[3];
    const float* w_q       = (const float*)d_in[4];
    const float* ln_feat_w = (const float*)d_in[5];
    const float* ln_feat_b = (const float*)d_in[6];
    const float* ln_slot_w = (const float*)d_in[7];
    const float* ln_slot_b = (const float*)d_in[8];
    const float* gru_w_ih  = (const float*)d_in[9];
    const float* gru_w_hh  = (const float*)d_in[10];
    const float* gru_b_ih  = (const float*)d_in[11];
    const float* gru_b_hh  = (const float*)d_in[12];
    const float* ln_mlp_w  = (const float*)d_in[13];
    const float* ln_mlp_b  = (const float*)d_in[14];
    const float* mlp_w1    = (const float*)d_in[15];
    const float* mlp_b1    = (const float*)d_in[16];
    const float* mlp_w2    = (const float*)d_in[17];
    const float* mlp_b2    = (const float*)d_in[18];

    float* out  = (float*)d_out;
    float* attn = out + kBS * kD;

    float *wqk, *wvih, *whht, *sn, *attnf, *upart, *dpart,
          *slots, *tbuf, *h1, *part;
    cudaGetSymbolAddress((void**)&wqk,   g_wqk);
    cudaGetSymbolAddress((void**)&wvih,  g_wvih);
    cudaGetSymbolAddress((void**)&whht,  g_whht);
    cudaGetSymbolAddress((void**)&sn,    g_sn);
    cudaGetSymbolAddress((void**)&attnf, g_attnf);
    cudaGetSymbolAddress((void**)&upart, g_upart);
    cudaGetSymbolAddress((void**)&dpart, g_dpart);
    cudaGetSymbolAddress((void**)&slots, g_slots);
    cudaGetSymbolAddress((void**)&tbuf,  g_tbuf);
    cudaGetSymbolAddress((void**)&h1,    g_h1);
    cudaGetSymbolAddress((void**)&part,  g_part);

    cudaFuncSetAttribute(fused_attn, cudaFuncAttributeMaxDynamicSharedMemorySize, FA_SMEM);

    const size_t MNg = (size_t)kBS * 3 * kD;

    // ---- prologue ----
    copy4_kernel<<<(kBS * kD / 4 + 255) / 256, 256>>>((float4*)slots, (const float4*)slots_in, kBS * kD / 4);
    ln_kernel<<<kBS, 128>>>(slots, ln_slot_w, ln_slot_b, sn);
    transpose_kernel<<<dim3(16, 48), 256>>>(gru_w_hh, whht);
    // wqk = w_q @ w_k^T, SK=8
    gemm_small<1><<<dim3(8, 8, 8), 128>>>(w_q, w_k, part, kD, kD, kD, 64);
    gemm_reduce<<<(kD * kD + 255) / 256, 256>>>(part, wqk, kD * kD, kD, 8, nullptr, 0);
    // wvih = w_v @ gru_w_ih^T, SK=8
    gemm_small<1><<<dim3(8, 24, 8), 128>>>(w_v, gru_w_ih, part, kD, 3 * kD, kD, 64);
    gemm_reduce<<<(kD * 3 * kD + 255) / 256, 256>>>(part, wvih, kD * 3 * kD, 3 * kD, 8, nullptr, 0);

    for (int it = 0; it < 3; ++it) {
        // q partials = sn @ wqk, SK=8 (summed inside fused_attn)
        gemm_small<0><<<dim3(4, 8, 8), 128>>>(sn, wqk, part, kBS, kD, kD, 64);
        fused_attn<<<dim3(8, kB), 256, FA_SMEM>>>(part, features, ln_feat_w, ln_feat_b,
                                                  attn, upart, dpart);
        attn_finish<<<kBS, 128>>>(upart, dpart, attnf);
        // gi partials z=0..7, gh partials z=8..15 (summed inside gru_ln)
        gemm_small<0><<<dim3(4, 24, 8), 128>>>(attnf, wvih, part, kBS, 3 * kD, kD, 64);
        gemm_small<0><<<dim3(4, 24, 8), 128>>>(sn, whht, part + 8 * MNg, kBS, 3 * kD, kD, 64);
        gru_ln_kernel<<<kBS, 128>>>(part, gru_b_ih, gru_b_hh, sn,
                                    ln_mlp_w, ln_mlp_b, slots, tbuf);
        // h1 = relu(tbuf @ mlp_w1 + b1), SK=8 + reduce
        gemm_small<0><<<dim3(4, 32, 8), 128>>>(tbuf, mlp_w1, part, kBS, kH, kD, 64);
        gemm_reduce<<<(kBS * kH + 255) / 256, 256>>>(part, h1, kBS * kH, kH, 8, mlp_b1, 1);
        // mlp2 partials SK=16 (summed + bias + residual + LN_slot in mlp2_ln)
        gemm_small<0><<<dim3(4, 8, 16), 128>>>(h1, mlp_w2, part, kBS, kD, kH, 128);
        mlp2_ln_kernel<<<kBS, 128>>>(part, mlp_b2, ln_slot_w, ln_slot_b, slots, sn);
    }

    copy4_kernel<<<(kBS * kD / 4 + 255) / 256, 256>>>((float4*)out, (const float4*)slots, kBS * kD / 4);
}